// round 6
// baseline (speedup 1.0000x reference)
#include <cuda_runtime.h>
#include <math.h>

#define BB 16
#define SS 2048
#define TT 1024
#define EE 256
#define DD 256

typedef unsigned long long u64;

// Scratch (static device globals: no allocation in kernel_launch)
__device__ __align__(16) float g_dec_proj[(size_t)BB * TT * EE];   // 16.8 MB
__device__ __align__(16) float g_context[(size_t)BB * TT * EE];    // 16.8 MB

// ---- packed f32x2 helpers ------------------------------------------------
__device__ __forceinline__ u64 dup2(float x) {
    u64 r; asm("mov.b64 %0, {%1, %1};" : "=l"(r) : "f"(x)); return r;
}
__device__ __forceinline__ void fma2(u64& d, u64 a, u64 b) {
    asm("fma.rn.f32x2 %0, %1, %2, %0;" : "+l"(d) : "l"(a), "l"(b));
}
__device__ __forceinline__ void mul2(u64& d, u64 a) {
    asm("mul.rn.f32x2 %0, %0, %1;" : "+l"(d) : "l"(a));
}
__device__ __forceinline__ float2 unpk(u64 v) {
    float a, b; asm("mov.b64 {%0, %1}, %2;" : "=f"(a), "=f"(b) : "l"(v));
    return make_float2(a, b);
}

// ---------------------------------------------------------------------------
// Kernel 1: dec_proj[b,t,:] = dec[b,t,:] @ W_enc^T   (M=B*T, K=D, N=E)
//   (scores = dec @ (enc W)^T == (dec W^T) @ enc^T — reassociated)
// 64x64 tile, 256 threads, 4x4 microtile via f32x2 pairs, K-tile 32.
// ---------------------------------------------------------------------------
__global__ __launch_bounds__(256) void k_dec_proj(const float* __restrict__ dec,
                                                  const float* __restrict__ W)
{
    __shared__ float Ast[32][68];   // transposed dec tile [d][t]
    __shared__ float Bs[32][68];    // W^T tile [d][e]

    const int tid = threadIdx.x;
    const int tx = tid & 15, ty = tid >> 4;
    const int m0 = blockIdx.y * 64, n0 = blockIdx.x * 64;

    u64 acc[2][4];
#pragma unroll
    for (int p = 0; p < 2; ++p)
#pragma unroll
        for (int j = 0; j < 4; ++j) acc[p][j] = 0ull;

    for (int k0 = 0; k0 < DD; k0 += 32) {
#pragma unroll
        for (int it = 0; it < 2; ++it) {
            int f = tid + it * 256;
            int m = f >> 3, k4 = (f & 7) * 4;
            float4 v = *(const float4*)(dec + (size_t)(m0 + m) * DD + k0 + k4);
            Ast[k4 + 0][m] = v.x; Ast[k4 + 1][m] = v.y;
            Ast[k4 + 2][m] = v.z; Ast[k4 + 3][m] = v.w;
        }
#pragma unroll
        for (int it = 0; it < 2; ++it) {
            int f = tid + it * 256;
            int e = f >> 3, k4 = (f & 7) * 4;
            float4 v = *(const float4*)(W + (size_t)(n0 + e) * DD + k0 + k4);
            Bs[k4 + 0][e] = v.x; Bs[k4 + 1][e] = v.y;
            Bs[k4 + 2][e] = v.z; Bs[k4 + 3][e] = v.w;
        }
        __syncthreads();
#pragma unroll
        for (int k = 0; k < 32; ++k) {
            ulonglong2 a2 = *(const ulonglong2*)&Ast[k][ty * 4];
            float4 b = *(const float4*)&Bs[k][tx * 4];
            u64 b0 = dup2(b.x), b1 = dup2(b.y), b2 = dup2(b.z), b3 = dup2(b.w);
            fma2(acc[0][0], a2.x, b0); fma2(acc[1][0], a2.y, b0);
            fma2(acc[0][1], a2.x, b1); fma2(acc[1][1], a2.y, b1);
            fma2(acc[0][2], a2.x, b2); fma2(acc[1][2], a2.y, b2);
            fma2(acc[0][3], a2.x, b3); fma2(acc[1][3], a2.y, b3);
        }
        __syncthreads();
    }
    float2 u[2][4];
#pragma unroll
    for (int p = 0; p < 2; ++p)
#pragma unroll
        for (int j = 0; j < 4; ++j) u[p][j] = unpk(acc[p][j]);
    float* o = g_dec_proj + (size_t)(m0 + ty * 4) * EE + n0 + tx * 4;
    *(float4*)(o + 0 * EE) = make_float4(u[0][0].x, u[0][1].x, u[0][2].x, u[0][3].x);
    *(float4*)(o + 1 * EE) = make_float4(u[0][0].y, u[0][1].y, u[0][2].y, u[0][3].y);
    *(float4*)(o + 2 * EE) = make_float4(u[1][0].x, u[1][1].x, u[1][2].x, u[1][3].x);
    *(float4*)(o + 3 * EE) = make_float4(u[1][0].y, u[1][1].y, u[1][2].y, u[1][3].y);
}

// ---------------------------------------------------------------------------
// Kernel 2: fused flash-attention.
//   scores = dec_proj_tile @ enc_chunk^T (masked), online softmax over S,
//   context += softmax @ enc_chunk.  Single enc load feeds BOTH GEMMs.
// Transposed tiles stored at stride 64 with XOR swizzle  col ^ (e & 60):
//   float4 reads stay 16B-aligned & conflict-free; scatter STS 4-way max.
// ---------------------------------------------------------------------------
#define PADP 68
#define SMEM_ATTN_FLOATS (16384 + 16384 + 16384 + 64 * PADP + 64 + 64 + 64 + 64)
#define SMEM_ATTN_BYTES  (SMEM_ATTN_FLOATS * 4)

__global__ __launch_bounds__(256, 1) void k_attn(const float* __restrict__ encS,
                                                 const int* __restrict__ mask)
{
    extern __shared__ float sm[];
    float* sDecPT = sm;                    // [256 e][64 t] swizzled
    float* sEncT  = sm + 16384;            // [256 e][64 s] swizzled
    float* sEnc   = sm + 32768;            // [64 s][256 e] natural
    float* sP     = sm + 49152;            // [64 t][68]
    float* sM     = sP + 64 * PADP;
    float* sL     = sM + 64;
    float* sScale = sL + 64;
    int*   sMask  = (int*)(sScale + 64);

    const int tid = threadIdx.x;
    const int tx = tid & 15, ty = tid >> 4;
    const int b = blockIdx.y;
    const int t0 = blockIdx.x * 64;

    // Load dec_proj tile (64 t x 256 e) transposed+swizzled
    const float* dpBase = g_dec_proj + ((size_t)b * TT + t0) * EE;
#pragma unroll
    for (int it = 0; it < 16; ++it) {
        int f = tid + it * 256;
        int t = f >> 6, m = f & 63;
        int e4 = m * 4, swz = (m & 15) * 4;
        float4 v = *(const float4*)(dpBase + (size_t)t * EE + e4);
        int tc = t ^ swz;
        sDecPT[(e4 + 0) * 64 + tc] = v.x;
        sDecPT[(e4 + 1) * 64 + tc] = v.y;
        sDecPT[(e4 + 2) * 64 + tc] = v.z;
        sDecPT[(e4 + 3) * 64 + tc] = v.w;
    }
    if (tid < 64) { sM[tid] = -INFINITY; sL[tid] = 0.f; }

    u64 acc[4][8];   // context: rows ty*4+i, col pairs (g*4+{0,1}),(g*4+{2,3})
#pragma unroll
    for (int i = 0; i < 4; ++i)
#pragma unroll
        for (int c = 0; c < 8; ++c) acc[i][c] = 0ull;

    for (int s0 = 0; s0 < SS; s0 += 64) {
        __syncthreads();   // protect sEnc/sEncT/sP from previous-iter readers

        // Single enc chunk load -> natural + transposed-swizzled copies
        const float* eBase = encS + ((size_t)b * SS + s0) * EE;
#pragma unroll
        for (int it = 0; it < 16; ++it) {
            int f = tid + it * 256;
            int s = f >> 6, m = f & 63;
            int e4 = m * 4, swz = (m & 15) * 4;
            float4 v = *(const float4*)(eBase + (size_t)s * EE + e4);
            *(float4*)&sEnc[s * EE + e4] = v;
            int scc = s ^ swz;
            sEncT[(e4 + 0) * 64 + scc] = v.x;
            sEncT[(e4 + 1) * 64 + scc] = v.y;
            sEncT[(e4 + 2) * 64 + scc] = v.z;
            sEncT[(e4 + 3) * 64 + scc] = v.w;
        }
        if (tid < 64) sMask[tid] = mask[(size_t)b * SS + s0 + tid];
        __syncthreads();

        // GEMM1: scores[64 t][64 s] = decP_tile @ enc_chunk^T  (K=E=256)
        u64 sc2[2][4];
#pragma unroll
        for (int p = 0; p < 2; ++p)
#pragma unroll
            for (int j = 0; j < 4; ++j) sc2[p][j] = 0ull;
#pragma unroll 16
        for (int e = 0; e < 256; ++e) {
            int swz = e & 60;
            ulonglong2 a2 = *(const ulonglong2*)&sDecPT[e * 64 + ((ty * 4) ^ swz)];
            float4 b4 = *(const float4*)&sEncT[e * 64 + ((tx * 4) ^ swz)];
            u64 b0 = dup2(b4.x), b1 = dup2(b4.y), b2 = dup2(b4.z), b3 = dup2(b4.w);
            fma2(sc2[0][0], a2.x, b0); fma2(sc2[1][0], a2.y, b0);
            fma2(sc2[0][1], a2.x, b1); fma2(sc2[1][1], a2.y, b1);
            fma2(sc2[0][2], a2.x, b2); fma2(sc2[1][2], a2.y, b2);
            fma2(sc2[0][3], a2.x, b3); fma2(sc2[1][3], a2.y, b3);
        }
        float sc[4][4];
#pragma unroll
        for (int j = 0; j < 4; ++j) {
            float2 lo = unpk(sc2[0][j]), hi = unpk(sc2[1][j]);
            sc[0][j] = lo.x; sc[1][j] = lo.y; sc[2][j] = hi.x; sc[3][j] = hi.y;
        }

        // Mask + stage scores
#pragma unroll
        for (int j = 0; j < 4; ++j) {
            bool mj = sMask[tx * 4 + j] != 0;
#pragma unroll
            for (int i = 0; i < 4; ++i)
                sP[(ty * 4 + i) * PADP + tx * 4 + j] = mj ? sc[i][j] : -INFINITY;
        }
        __syncthreads();

        // Online softmax: 4 lanes per row, 16 cols each
        {
            int r = tid >> 2, q = tid & 3;
            float* row = sP + r * PADP + q * 16;
            float v[16];
            float mloc = -INFINITY;
#pragma unroll
            for (int j = 0; j < 16; ++j) { v[j] = row[j]; mloc = fmaxf(mloc, v[j]); }
            mloc = fmaxf(mloc, __shfl_xor_sync(0xffffffffu, mloc, 1));
            mloc = fmaxf(mloc, __shfl_xor_sync(0xffffffffu, mloc, 2));
            float mold = sM[r];
            float mnew = fmaxf(mold, mloc);
            float scale = 1.f, sum = 0.f;
            if (mnew == -INFINITY) {
#pragma unroll
                for (int j = 0; j < 16; ++j) v[j] = 0.f;
            } else {
                scale = __expf(mold - mnew);
#pragma unroll
                for (int j = 0; j < 16; ++j) { v[j] = __expf(v[j] - mnew); sum += v[j]; }
            }
            sum += __shfl_xor_sync(0xffffffffu, sum, 1);
            sum += __shfl_xor_sync(0xffffffffu, sum, 2);
#pragma unroll
            for (int j = 0; j < 16; ++j) row[j] = v[j];
            if (q == 0) { sM[r] = mnew; sL[r] = sL[r] * scale + sum; sScale[r] = scale; }
        }
        __syncthreads();

        // Rescale running context, then GEMM2: acc += P_chunk @ enc_chunk
        {
            u64 rs0 = dup2(sScale[ty * 4 + 0]);
            u64 rs1 = dup2(sScale[ty * 4 + 1]);
            u64 rs2 = dup2(sScale[ty * 4 + 2]);
            u64 rs3 = dup2(sScale[ty * 4 + 3]);
#pragma unroll
            for (int c = 0; c < 8; ++c) {
                mul2(acc[0][c], rs0); mul2(acc[1][c], rs1);
                mul2(acc[2][c], rs2); mul2(acc[3][c], rs3);
            }
        }
#pragma unroll 4
        for (int s = 0; s < 64; ++s) {
            u64 pd[4];
#pragma unroll
            for (int i = 0; i < 4; ++i) pd[i] = dup2(sP[(ty * 4 + i) * PADP + s]);
#pragma unroll
            for (int g = 0; g < 4; ++g) {
                ulonglong2 ee = *(const ulonglong2*)&sEnc[s * EE + g * 64 + tx * 4];
#pragma unroll
                for (int i = 0; i < 4; ++i) {
                    fma2(acc[i][g * 2 + 0], pd[i], ee.x);
                    fma2(acc[i][g * 2 + 1], pd[i], ee.y);
                }
            }
        }
    }

    // Normalize + write context
    float inv[4];
#pragma unroll
    for (int i = 0; i < 4; ++i) inv[i] = 1.f / sL[ty * 4 + i];
    float* cBase = g_context + ((size_t)b * TT + t0) * EE;
#pragma unroll
    for (int i = 0; i < 4; ++i) {
#pragma unroll
        for (int g = 0; g < 4; ++g) {
            float2 lo = unpk(acc[i][g * 2 + 0]);
            float2 hi = unpk(acc[i][g * 2 + 1]);
            float4 v = make_float4(lo.x * inv[i], lo.y * inv[i], hi.x * inv[i], hi.y * inv[i]);
            *(float4*)(cBase + (size_t)(ty * 4 + i) * EE + g * 64 + tx * 4) = v;
        }
    }
}

// ---------------------------------------------------------------------------
// Kernel 3: out = tanh( [context, dec] @ W_fin )   (M=B*T, K=512, N=D)
// ---------------------------------------------------------------------------
__global__ __launch_bounds__(256) void k_final(const float* __restrict__ dec,
                                               const float* __restrict__ Wfin,
                                               float* __restrict__ out)
{
    __shared__ float Ast[32][68];
    __shared__ float Bs[32][68];

    const int tid = threadIdx.x;
    const int tx = tid & 15, ty = tid >> 4;
    const int m0 = blockIdx.y * 64, n0 = blockIdx.x * 64;

    u64 acc[2][4];
#pragma unroll
    for (int p = 0; p < 2; ++p)
#pragma unroll
        for (int j = 0; j < 4; ++j) acc[p][j] = 0ull;

    for (int kt = 0; kt < 16; ++kt) {
        int k0 = kt * 32;
        const float* src = (k0 < 256) ? g_context : dec;
        int koff = (k0 < 256) ? k0 : (k0 - 256);
#pragma unroll
        for (int it = 0; it < 2; ++it) {
            int f = tid + it * 256;
            int m = f >> 3, k4 = (f & 7) * 4;
            float4 v = *(const float4*)(src + (size_t)(m0 + m) * 256 + koff + k4);
            Ast[k4 + 0][m] = v.x; Ast[k4 + 1][m] = v.y;
            Ast[k4 + 2][m] = v.z; Ast[k4 + 3][m] = v.w;
        }
#pragma unroll
        for (int it = 0; it < 2; ++it) {
            int f = tid + it * 256;
            int k = f >> 4, n4 = (f & 15) * 4;
            *(float4*)&Bs[k][n4] = *(const float4*)(Wfin + (size_t)(k0 + k) * DD + n0 + n4);
        }
        __syncthreads();
#pragma unroll
        for (int k = 0; k < 32; ++k) {
            ulonglong2 a2 = *(const ulonglong2*)&Ast[k][ty * 4];
            float4 b = *(const float4*)&Bs[k][tx * 4];
            u64 b0 = dup2(b.x), b1 = dup2(b.y), b2 = dup2(b.z), b3 = dup2(b.w);
            fma2(acc[0][0], a2.x, b0); fma2(acc[1][0], a2.y, b0);
            fma2(acc[0][1], a2.x, b1); fma2(acc[1][1], a2.y, b1);
            fma2(acc[0][2], a2.x, b2); fma2(acc[1][2], a2.y, b2);
            fma2(acc[0][3], a2.x, b3); fma2(acc[1][3], a2.y, b3);
        }
        __syncthreads();
    }
    float2 u[2][4];
#pragma unroll
    for (int p = 0; p < 2; ++p)
#pragma unroll
        for (int j = 0; j < 4; ++j) u[p][j] = unpk(acc[p][j]);
    float* o = out + (size_t)(m0 + ty * 4) * DD + n0 + tx * 4;
    *(float4*)(o + 0 * DD) = make_float4(tanhf(u[0][0].x), tanhf(u[0][1].x), tanhf(u[0][2].x), tanhf(u[0][3].x));
    *(float4*)(o + 1 * DD) = make_float4(tanhf(u[0][0].y), tanhf(u[0][1].y), tanhf(u[0][2].y), tanhf(u[0][3].y));
    *(float4*)(o + 2 * DD) = make_float4(tanhf(u[1][0].x), tanhf(u[1][1].x), tanhf(u[1][2].x), tanhf(u[1][3].x));
    *(float4*)(o + 3 * DD) = make_float4(tanhf(u[1][0].y), tanhf(u[1][1].y), tanhf(u[1][2].y), tanhf(u[1][3].y));
}

// ---------------------------------------------------------------------------
extern "C" void kernel_launch(void* const* d_in, const int* in_sizes, int n_in,
                              void* d_out, int out_size)
{
    const float* enc  = (const float*)d_in[0];   // (B,S,E)
    const float* dec  = (const float*)d_in[1];   // (B,T,D)
    const int*   mask = (const int*)d_in[2];     // (B,S) bool -> int32
    const float* Wenc = (const float*)d_in[3];   // (E,D)
    const float* Wfin = (const float*)d_in[4];   // (E+D,D)
    float* out = (float*)d_out;                  // (B,T,D)

    cudaFuncSetAttribute(k_attn, cudaFuncAttributeMaxDynamicSharedMemorySize, SMEM_ATTN_BYTES);

    k_dec_proj<<<dim3(EE / 64, (BB * TT) / 64), 256>>>(dec, Wenc);
    k_attn<<<dim3(TT / 64, BB), 256, SMEM_ATTN_BYTES>>>(enc, mask);
    k_final<<<dim3(DD / 64, (BB * TT) / 64), 256>>>(dec, Wfin, out);
}

// round 7
// speedup vs baseline: 1.0001x; 1.0001x over previous
#include <cuda_runtime.h>
#include <math.h>

#define BB 16
#define SS 2048
#define TT 1024
#define EE 256
#define DD 256

typedef unsigned long long u64;

// Scratch (static device globals: no allocation in kernel_launch)
__device__ __align__(16) float g_dec_proj[(size_t)BB * TT * EE];   // 16.8 MB
__device__ __align__(16) float g_context[(size_t)BB * TT * EE];    // 16.8 MB

// ---- packed f32x2 helpers ------------------------------------------------
__device__ __forceinline__ u64 dup2(float x) {
    u64 r; asm("mov.b64 %0, {%1, %1};" : "=l"(r) : "f"(x)); return r;
}
__device__ __forceinline__ void fma2(u64& d, u64 a, u64 b) {
    asm("fma.rn.f32x2 %0, %1, %2, %0;" : "+l"(d) : "l"(a), "l"(b));
}
__device__ __forceinline__ void mul2(u64& d, u64 a) {
    asm("mul.rn.f32x2 %0, %0, %1;" : "+l"(d) : "l"(a));
}
__device__ __forceinline__ float2 unpk(u64 v) {
    float a, b; asm("mov.b64 {%0, %1}, %2;" : "=f"(a), "=f"(b) : "l"(v));
    return make_float2(a, b);
}

// ---------------------------------------------------------------------------
// Kernel 1: dec_proj[b,t,:] = dec[b,t,:] @ W_enc^T   (M=B*T, K=D, N=E)
//   (scores = dec @ (enc W)^T == (dec W^T) @ enc^T — reassociated)
// 64x64 tile, 256 threads, 4x4 microtile via f32x2 pairs, K-tile 32.
// ---------------------------------------------------------------------------
__global__ __launch_bounds__(256) void k_dec_proj(const float* __restrict__ dec,
                                                  const float* __restrict__ W)
{
    __shared__ float Ast[32][68];   // transposed dec tile [d][t]
    __shared__ float Bs[32][68];    // W^T tile [d][e]

    const int tid = threadIdx.x;
    const int tx = tid & 15, ty = tid >> 4;
    const int m0 = blockIdx.y * 64, n0 = blockIdx.x * 64;

    u64 acc[2][4];
#pragma unroll
    for (int p = 0; p < 2; ++p)
#pragma unroll
        for (int j = 0; j < 4; ++j) acc[p][j] = 0ull;

    for (int k0 = 0; k0 < DD; k0 += 32) {
#pragma unroll
        for (int it = 0; it < 2; ++it) {
            int f = tid + it * 256;
            int m = f >> 3, k4 = (f & 7) * 4;
            float4 v = *(const float4*)(dec + (size_t)(m0 + m) * DD + k0 + k4);
            Ast[k4 + 0][m] = v.x; Ast[k4 + 1][m] = v.y;
            Ast[k4 + 2][m] = v.z; Ast[k4 + 3][m] = v.w;
        }
#pragma unroll
        for (int it = 0; it < 2; ++it) {
            int f = tid + it * 256;
            int e = f >> 3, k4 = (f & 7) * 4;
            float4 v = *(const float4*)(W + (size_t)(n0 + e) * DD + k0 + k4);
            Bs[k4 + 0][e] = v.x; Bs[k4 + 1][e] = v.y;
            Bs[k4 + 2][e] = v.z; Bs[k4 + 3][e] = v.w;
        }
        __syncthreads();
#pragma unroll
        for (int k = 0; k < 32; ++k) {
            ulonglong2 a2 = *(const ulonglong2*)&Ast[k][ty * 4];
            float4 b = *(const float4*)&Bs[k][tx * 4];
            u64 b0 = dup2(b.x), b1 = dup2(b.y), b2 = dup2(b.z), b3 = dup2(b.w);
            fma2(acc[0][0], a2.x, b0); fma2(acc[1][0], a2.y, b0);
            fma2(acc[0][1], a2.x, b1); fma2(acc[1][1], a2.y, b1);
            fma2(acc[0][2], a2.x, b2); fma2(acc[1][2], a2.y, b2);
            fma2(acc[0][3], a2.x, b3); fma2(acc[1][3], a2.y, b3);
        }
        __syncthreads();
    }
    float2 u[2][4];
#pragma unroll
    for (int p = 0; p < 2; ++p)
#pragma unroll
        for (int j = 0; j < 4; ++j) u[p][j] = unpk(acc[p][j]);
    float* o = g_dec_proj + (size_t)(m0 + ty * 4) * EE + n0 + tx * 4;
    *(float4*)(o + 0 * EE) = make_float4(u[0][0].x, u[0][1].x, u[0][2].x, u[0][3].x);
    *(float4*)(o + 1 * EE) = make_float4(u[0][0].y, u[0][1].y, u[0][2].y, u[0][3].y);
    *(float4*)(o + 2 * EE) = make_float4(u[1][0].x, u[1][1].x, u[1][2].x, u[1][3].x);
    *(float4*)(o + 3 * EE) = make_float4(u[1][0].y, u[1][1].y, u[1][2].y, u[1][3].y);
}

// ---------------------------------------------------------------------------
// Kernel 2: fused flash-attention.
//   scores = dec_proj_tile @ enc_chunk^T (masked), online softmax over S,
//   context += softmax @ enc_chunk.  Single enc load feeds BOTH GEMMs.
// Transposed tiles stored at stride 64 with XOR swizzle  col ^ (e & 60):
//   float4 reads stay 16B-aligned & conflict-free; scatter STS 4-way max.
// ---------------------------------------------------------------------------
#define PADP 68
#define SMEM_ATTN_FLOATS (16384 + 16384 + 16384 + 64 * PADP + 64 + 64 + 64 + 64)
#define SMEM_ATTN_BYTES  (SMEM_ATTN_FLOATS * 4)

__global__ __launch_bounds__(256, 1) void k_attn(const float* __restrict__ encS,
                                                 const int* __restrict__ mask)
{
    extern __shared__ float sm[];
    float* sDecPT = sm;                    // [256 e][64 t] swizzled
    float* sEncT  = sm + 16384;            // [256 e][64 s] swizzled
    float* sEnc   = sm + 32768;            // [64 s][256 e] natural
    float* sP     = sm + 49152;            // [64 t][68]
    float* sM     = sP + 64 * PADP;
    float* sL     = sM + 64;
    float* sScale = sL + 64;
    int*   sMask  = (int*)(sScale + 64);

    const int tid = threadIdx.x;
    const int tx = tid & 15, ty = tid >> 4;
    const int b = blockIdx.y;
    const int t0 = blockIdx.x * 64;

    // Load dec_proj tile (64 t x 256 e) transposed+swizzled
    const float* dpBase = g_dec_proj + ((size_t)b * TT + t0) * EE;
#pragma unroll
    for (int it = 0; it < 16; ++it) {
        int f = tid + it * 256;
        int t = f >> 6, m = f & 63;
        int e4 = m * 4, swz = (m & 15) * 4;
        float4 v = *(const float4*)(dpBase + (size_t)t * EE + e4);
        int tc = t ^ swz;
        sDecPT[(e4 + 0) * 64 + tc] = v.x;
        sDecPT[(e4 + 1) * 64 + tc] = v.y;
        sDecPT[(e4 + 2) * 64 + tc] = v.z;
        sDecPT[(e4 + 3) * 64 + tc] = v.w;
    }
    if (tid < 64) { sM[tid] = -INFINITY; sL[tid] = 0.f; }

    u64 acc[4][8];   // context: rows ty*4+i, col pairs (g*4+{0,1}),(g*4+{2,3})
#pragma unroll
    for (int i = 0; i < 4; ++i)
#pragma unroll
        for (int c = 0; c < 8; ++c) acc[i][c] = 0ull;

    for (int s0 = 0; s0 < SS; s0 += 64) {
        __syncthreads();   // protect sEnc/sEncT/sP from previous-iter readers

        // Single enc chunk load -> natural + transposed-swizzled copies
        const float* eBase = encS + ((size_t)b * SS + s0) * EE;
#pragma unroll
        for (int it = 0; it < 16; ++it) {
            int f = tid + it * 256;
            int s = f >> 6, m = f & 63;
            int e4 = m * 4, swz = (m & 15) * 4;
            float4 v = *(const float4*)(eBase + (size_t)s * EE + e4);
            *(float4*)&sEnc[s * EE + e4] = v;
            int scc = s ^ swz;
            sEncT[(e4 + 0) * 64 + scc] = v.x;
            sEncT[(e4 + 1) * 64 + scc] = v.y;
            sEncT[(e4 + 2) * 64 + scc] = v.z;
            sEncT[(e4 + 3) * 64 + scc] = v.w;
        }
        if (tid < 64) sMask[tid] = mask[(size_t)b * SS + s0 + tid];
        __syncthreads();

        // GEMM1: scores[64 t][64 s] = decP_tile @ enc_chunk^T  (K=E=256)
        u64 sc2[2][4];
#pragma unroll
        for (int p = 0; p < 2; ++p)
#pragma unroll
            for (int j = 0; j < 4; ++j) sc2[p][j] = 0ull;
#pragma unroll 16
        for (int e = 0; e < 256; ++e) {
            int swz = e & 60;
            ulonglong2 a2 = *(const ulonglong2*)&sDecPT[e * 64 + ((ty * 4) ^ swz)];
            float4 b4 = *(const float4*)&sEncT[e * 64 + ((tx * 4) ^ swz)];
            u64 b0 = dup2(b4.x), b1 = dup2(b4.y), b2 = dup2(b4.z), b3 = dup2(b4.w);
            fma2(sc2[0][0], a2.x, b0); fma2(sc2[1][0], a2.y, b0);
            fma2(sc2[0][1], a2.x, b1); fma2(sc2[1][1], a2.y, b1);
            fma2(sc2[0][2], a2.x, b2); fma2(sc2[1][2], a2.y, b2);
            fma2(sc2[0][3], a2.x, b3); fma2(sc2[1][3], a2.y, b3);
        }
        float sc[4][4];
#pragma unroll
        for (int j = 0; j < 4; ++j) {
            float2 lo = unpk(sc2[0][j]), hi = unpk(sc2[1][j]);
            sc[0][j] = lo.x; sc[1][j] = lo.y; sc[2][j] = hi.x; sc[3][j] = hi.y;
        }

        // Mask + stage scores
#pragma unroll
        for (int j = 0; j < 4; ++j) {
            bool mj = sMask[tx * 4 + j] != 0;
#pragma unroll
            for (int i = 0; i < 4; ++i)
                sP[(ty * 4 + i) * PADP + tx * 4 + j] = mj ? sc[i][j] : -INFINITY;
        }
        __syncthreads();

        // Online softmax: 4 lanes per row, 16 cols each
        {
            int r = tid >> 2, q = tid & 3;
            float* row = sP + r * PADP + q * 16;
            float v[16];
            float mloc = -INFINITY;
#pragma unroll
            for (int j = 0; j < 16; ++j) { v[j] = row[j]; mloc = fmaxf(mloc, v[j]); }
            mloc = fmaxf(mloc, __shfl_xor_sync(0xffffffffu, mloc, 1));
            mloc = fmaxf(mloc, __shfl_xor_sync(0xffffffffu, mloc, 2));
            float mold = sM[r];
            float mnew = fmaxf(mold, mloc);
            float scale = 1.f, sum = 0.f;
            if (mnew == -INFINITY) {
#pragma unroll
                for (int j = 0; j < 16; ++j) v[j] = 0.f;
            } else {
                scale = __expf(mold - mnew);
#pragma unroll
                for (int j = 0; j < 16; ++j) { v[j] = __expf(v[j] - mnew); sum += v[j]; }
            }
            sum += __shfl_xor_sync(0xffffffffu, sum, 1);
            sum += __shfl_xor_sync(0xffffffffu, sum, 2);
#pragma unroll
            for (int j = 0; j < 16; ++j) row[j] = v[j];
            if (q == 0) { sM[r] = mnew; sL[r] = sL[r] * scale + sum; sScale[r] = scale; }
        }
        __syncthreads();

        // Rescale running context, then GEMM2: acc += P_chunk @ enc_chunk
        {
            u64 rs0 = dup2(sScale[ty * 4 + 0]);
            u64 rs1 = dup2(sScale[ty * 4 + 1]);
            u64 rs2 = dup2(sScale[ty * 4 + 2]);
            u64 rs3 = dup2(sScale[ty * 4 + 3]);
#pragma unroll
            for (int c = 0; c < 8; ++c) {
                mul2(acc[0][c], rs0); mul2(acc[1][c], rs1);
                mul2(acc[2][c], rs2); mul2(acc[3][c], rs3);
            }
        }
#pragma unroll 4
        for (int s = 0; s < 64; ++s) {
            u64 pd[4];
#pragma unroll
            for (int i = 0; i < 4; ++i) pd[i] = dup2(sP[(ty * 4 + i) * PADP + s]);
#pragma unroll
            for (int g = 0; g < 4; ++g) {
                ulonglong2 ee = *(const ulonglong2*)&sEnc[s * EE + g * 64 + tx * 4];
#pragma unroll
                for (int i = 0; i < 4; ++i) {
                    fma2(acc[i][g * 2 + 0], pd[i], ee.x);
                    fma2(acc[i][g * 2 + 1], pd[i], ee.y);
                }
            }
        }
    }

    // Normalize + write context
    float inv[4];
#pragma unroll
    for (int i = 0; i < 4; ++i) inv[i] = 1.f / sL[ty * 4 + i];
    float* cBase = g_context + ((size_t)b * TT + t0) * EE;
#pragma unroll
    for (int i = 0; i < 4; ++i) {
#pragma unroll
        for (int g = 0; g < 4; ++g) {
            float2 lo = unpk(acc[i][g * 2 + 0]);
            float2 hi = unpk(acc[i][g * 2 + 1]);
            float4 v = make_float4(lo.x * inv[i], lo.y * inv[i], hi.x * inv[i], hi.y * inv[i]);
            *(float4*)(cBase + (size_t)(ty * 4 + i) * EE + g * 64 + tx * 4) = v;
        }
    }
}

// ---------------------------------------------------------------------------
// Kernel 3: out = tanh( [context, dec] @ W_fin )   (M=B*T, K=512, N=D)
// ---------------------------------------------------------------------------
__global__ __launch_bounds__(256) void k_final(const float* __restrict__ dec,
                                               const float* __restrict__ Wfin,
                                               float* __restrict__ out)
{
    __shared__ float Ast[32][68];
    __shared__ float Bs[32][68];

    const int tid = threadIdx.x;
    const int tx = tid & 15, ty = tid >> 4;
    const int m0 = blockIdx.y * 64, n0 = blockIdx.x * 64;

    u64 acc[2][4];
#pragma unroll
    for (int p = 0; p < 2; ++p)
#pragma unroll
        for (int j = 0; j < 4; ++j) acc[p][j] = 0ull;

    for (int kt = 0; kt < 16; ++kt) {
        int k0 = kt * 32;
        const float* src = (k0 < 256) ? g_context : dec;
        int koff = (k0 < 256) ? k0 : (k0 - 256);
#pragma unroll
        for (int it = 0; it < 2; ++it) {
            int f = tid + it * 256;
            int m = f >> 3, k4 = (f & 7) * 4;
            float4 v = *(const float4*)(src + (size_t)(m0 + m) * 256 + koff + k4);
            Ast[k4 + 0][m] = v.x; Ast[k4 + 1][m] = v.y;
            Ast[k4 + 2][m] = v.z; Ast[k4 + 3][m] = v.w;
        }
#pragma unroll
        for (int it = 0; it < 2; ++it) {
            int f = tid + it * 256;
            int k = f >> 4, n4 = (f & 15) * 4;
            *(float4*)&Bs[k][n4] = *(const float4*)(Wfin + (size_t)(k0 + k) * DD + n0 + n4);
        }
        __syncthreads();
#pragma unroll
        for (int k = 0; k < 32; ++k) {
            ulonglong2 a2 = *(const ulonglong2*)&Ast[k][ty * 4];
            float4 b = *(const float4*)&Bs[k][tx * 4];
            u64 b0 = dup2(b.x), b1 = dup2(b.y), b2 = dup2(b.z), b3 = dup2(b.w);
            fma2(acc[0][0], a2.x, b0); fma2(acc[1][0], a2.y, b0);
            fma2(acc[0][1], a2.x, b1); fma2(acc[1][1], a2.y, b1);
            fma2(acc[0][2], a2.x, b2); fma2(acc[1][2], a2.y, b2);
            fma2(acc[0][3], a2.x, b3); fma2(acc[1][3], a2.y, b3);
        }
        __syncthreads();
    }
    float2 u[2][4];
#pragma unroll
    for (int p = 0; p < 2; ++p)
#pragma unroll
        for (int j = 0; j < 4; ++j) u[p][j] = unpk(acc[p][j]);
    float* o = out + (size_t)(m0 + ty * 4) * DD + n0 + tx * 4;
    *(float4*)(o + 0 * DD) = make_float4(tanhf(u[0][0].x), tanhf(u[0][1].x), tanhf(u[0][2].x), tanhf(u[0][3].x));
    *(float4*)(o + 1 * DD) = make_float4(tanhf(u[0][0].y), tanhf(u[0][1].y), tanhf(u[0][2].y), tanhf(u[0][3].y));
    *(float4*)(o + 2 * DD) = make_float4(tanhf(u[1][0].x), tanhf(u[1][1].x), tanhf(u[1][2].x), tanhf(u[1][3].x));
    *(float4*)(o + 3 * DD) = make_float4(tanhf(u[1][0].y), tanhf(u[1][1].y), tanhf(u[1][2].y), tanhf(u[1][3].y));
}

// ---------------------------------------------------------------------------
extern "C" void kernel_launch(void* const* d_in, const int* in_sizes, int n_in,
                              void* d_out, int out_size)
{
    const float* enc  = (const float*)d_in[0];   // (B,S,E)
    const float* dec  = (const float*)d_in[1];   // (B,T,D)
    const int*   mask = (const int*)d_in[2];     // (B,S) bool -> int32
    const float* Wenc = (const float*)d_in[3];   // (E,D)
    const float* Wfin = (const float*)d_in[4];   // (E+D,D)
    float* out = (float*)d_out;                  // (B,T,D)

    cudaFuncSetAttribute(k_attn, cudaFuncAttributeMaxDynamicSharedMemorySize, SMEM_ATTN_BYTES);

    k_dec_proj<<<dim3(EE / 64, (BB * TT) / 64), 256>>>(dec, Wenc);
    k_attn<<<dim3(TT / 64, BB), 256, SMEM_ATTN_BYTES>>>(enc, mask);
    k_final<<<dim3(DD / 64, (BB * TT) / 64), 256>>>(dec, Wfin, out);
}

// round 11
// speedup vs baseline: 2.3734x; 2.3731x over previous
#include <cuda_runtime.h>
#include <cuda_bf16.h>
#include <math.h>
#include <stdint.h>

#define BB 16
#define SS 2048
#define TT 1024
#define EE 256
#define DD 256

typedef unsigned long long u64;

__device__ __align__(16) float g_dec_proj[(size_t)BB * TT * EE];
__device__ __align__(16) float g_context[(size_t)BB * TT * EE];

// ---- packed f32x2 helpers (scalar GEMMs) ----------------------------------
__device__ __forceinline__ u64 dup2(float x) {
    u64 r; asm("mov.b64 %0, {%1, %1};" : "=l"(r) : "f"(x)); return r;
}
__device__ __forceinline__ void fma2(u64& d, u64 a, u64 b) {
    asm("fma.rn.f32x2 %0, %1, %2, %0;" : "+l"(d) : "l"(a), "l"(b));
}
__device__ __forceinline__ float2 unpk(u64 v) {
    float a, b; asm("mov.b64 {%0, %1}, %2;" : "=f"(a), "=f"(b) : "l"(v));
    return make_float2(a, b);
}
// ---- bf16 helpers ---------------------------------------------------------
__device__ __forceinline__ void sp2(float a, float b, uint32_t& h, uint32_t& l) {
    __nv_bfloat162 hb = __floats2bfloat162_rn(a, b);
    float2 hf = __bfloat1622float2(hb);
    __nv_bfloat162 lb = __floats2bfloat162_rn(a - hf.x, b - hf.y);
    h = *(uint32_t*)&hb; l = *(uint32_t*)&lb;
}
__device__ __forceinline__ void mmab(float* d, const uint32_t* a, const uint32_t* b) {
    asm volatile("mma.sync.aligned.m16n8k16.row.col.f32.bf16.bf16.f32 "
        "{%0,%1,%2,%3}, {%4,%5,%6,%7}, {%8,%9}, {%0,%1,%2,%3};"
        : "+f"(d[0]), "+f"(d[1]), "+f"(d[2]), "+f"(d[3])
        : "r"(a[0]), "r"(a[1]), "r"(a[2]), "r"(a[3]), "r"(b[0]), "r"(b[1]));
}
__device__ __forceinline__ uint32_t ldA(const uint16_t* base, int r, int c) {   // 256-wide
    return *(const uint32_t*)&base[r * 256 + (c ^ ((r & 7) << 3))];
}
__device__ __forceinline__ uint32_t ldT(const uint16_t* base, int r, int c) {   // 64-wide
    return *(const uint32_t*)&base[r * 64 + (c ^ ((r & 7) << 3))];
}

// ---------------------------------------------------------------------------
// Kernel 1: dec_proj = dec @ W_enc^T (fp32 scalar, f32x2)
// ---------------------------------------------------------------------------
__global__ __launch_bounds__(256) void k_dec_proj(const float* __restrict__ dec,
                                                  const float* __restrict__ W)
{
    __shared__ float Ast[32][68];
    __shared__ float Bs[32][68];
    const int tid = threadIdx.x;
    const int tx = tid & 15, ty = tid >> 4;
    const int m0 = blockIdx.y * 64, n0 = blockIdx.x * 64;

    u64 acc[2][4];
#pragma unroll
    for (int p = 0; p < 2; ++p)
#pragma unroll
        for (int j = 0; j < 4; ++j) acc[p][j] = 0ull;

    for (int k0 = 0; k0 < DD; k0 += 32) {
#pragma unroll
        for (int it = 0; it < 2; ++it) {
            int f = tid + it * 256;
            int m = f >> 3, k4 = (f & 7) * 4;
            float4 v = *(const float4*)(dec + (size_t)(m0 + m) * DD + k0 + k4);
            Ast[k4 + 0][m] = v.x; Ast[k4 + 1][m] = v.y;
            Ast[k4 + 2][m] = v.z; Ast[k4 + 3][m] = v.w;
        }
#pragma unroll
        for (int it = 0; it < 2; ++it) {
            int f = tid + it * 256;
            int e = f >> 3, k4 = (f & 7) * 4;
            float4 v = *(const float4*)(W + (size_t)(n0 + e) * DD + k0 + k4);
            Bs[k4 + 0][e] = v.x; Bs[k4 + 1][e] = v.y;
            Bs[k4 + 2][e] = v.z; Bs[k4 + 3][e] = v.w;
        }
        __syncthreads();
#pragma unroll
        for (int k = 0; k < 32; ++k) {
            ulonglong2 a2 = *(const ulonglong2*)&Ast[k][ty * 4];
            float4 b = *(const float4*)&Bs[k][tx * 4];
            u64 b0 = dup2(b.x), b1 = dup2(b.y), b2 = dup2(b.z), b3 = dup2(b.w);
            fma2(acc[0][0], a2.x, b0); fma2(acc[1][0], a2.y, b0);
            fma2(acc[0][1], a2.x, b1); fma2(acc[1][1], a2.y, b1);
            fma2(acc[0][2], a2.x, b2); fma2(acc[1][2], a2.y, b2);
            fma2(acc[0][3], a2.x, b3); fma2(acc[1][3], a2.y, b3);
        }
        __syncthreads();
    }
    float2 u[2][4];
#pragma unroll
    for (int p = 0; p < 2; ++p)
#pragma unroll
        for (int j = 0; j < 4; ++j) u[p][j] = unpk(acc[p][j]);
    float* o = g_dec_proj + (size_t)(m0 + ty * 4) * EE + n0 + tx * 4;
    *(float4*)(o + 0 * EE) = make_float4(u[0][0].x, u[0][1].x, u[0][2].x, u[0][3].x);
    *(float4*)(o + 1 * EE) = make_float4(u[0][0].y, u[0][1].y, u[0][2].y, u[0][3].y);
    *(float4*)(o + 2 * EE) = make_float4(u[1][0].x, u[1][1].x, u[1][2].x, u[1][3].x);
    *(float4*)(o + 3 * EE) = make_float4(u[1][0].y, u[1][1].y, u[1][2].y, u[1][3].y);
}

// ---------------------------------------------------------------------------
// Kernel 2: mma.sync bf16 split-precision flash attention.
// grid (16 ttiles, 16 b), 256 threads (8 warps: 2 t-strips x 4 s/e-strips).
// ---------------------------------------------------------------------------
#define SMEM_ATTN_BYTES 230912

__global__ __launch_bounds__(256, 1) void k_attn(const float* __restrict__ encS,
                                                 const int* __restrict__ mask)
{
    extern __shared__ unsigned char smraw[];
    uint16_t* eH = (uint16_t*)smraw;          // enc hi  [64 s][256 e] swizzled
    uint16_t* eL = eH + 16384;                // enc lo
    uint16_t* tH = eL + 16384;                // encT hi [256 e][64 s]
    uint16_t* tL = tH + 16384;
    uint16_t* dH = tL + 16384;                // decP hi [64 t][256 e]
    uint16_t* dL = dH + 16384;
    float* sP   = (float*)(dL + 16384);       // [64 t][66] fp32 scores/probs
    float* sM   = sP + 64 * 66;
    float* sLs  = sM + 64;
    float* sSc  = sLs + 64;
    int* sMask  = (int*)(sSc + 64);
    uint16_t* pH = (uint16_t*)(sMask + 64);   // P hi [64 t][64 s] swizzled
    uint16_t* pL = pH + 4096;

    const int tid = threadIdx.x;
    const int wid = tid >> 5, lane = tid & 31;
    const int gid = lane >> 2, tig = lane & 3;
    const int wt = wid >> 2;      // t strip (0..1)
    const int ws = wid & 3;       // s strip (GEMM1) / e strip (GEMM2)
    const int b = blockIdx.y;
    const int t0 = blockIdx.x * 64;

    // decP tile -> bf16 hi/lo images (once)
    const float* dB = g_dec_proj + ((size_t)b * TT + t0) * EE;
#pragma unroll
    for (int it = 0; it < 16; ++it) {
        int f = tid + it * 256;
        int t = f >> 6, e4 = (f & 63) * 4;
        int c = e4 ^ ((t & 7) << 3);
        float4 v = *(const float4*)(dB + (size_t)t * EE + e4);
        uint32_t h, l;
        sp2(v.x, v.y, h, l); *(uint32_t*)&dH[t * 256 + c] = h;     *(uint32_t*)&dL[t * 256 + c] = l;
        sp2(v.z, v.w, h, l); *(uint32_t*)&dH[t * 256 + c + 2] = h; *(uint32_t*)&dL[t * 256 + c + 2] = l;
    }
    if (tid < 64) { sM[tid] = -INFINITY; sLs[tid] = 0.f; }

    float acc[2][8][4];
#pragma unroll
    for (int mt = 0; mt < 2; ++mt)
#pragma unroll
        for (int nt = 0; nt < 8; ++nt)
#pragma unroll
            for (int q = 0; q < 4; ++q) acc[mt][nt][q] = 0.f;

    for (int s0 = 0; s0 < SS; s0 += 64) {
        if (s0 > 0 && mask[(size_t)b * SS + s0] == 0) break;   // prefix mask
        __syncthreads();

        // enc chunk -> natural + transposed bf16 hi/lo images
        const float* eB = encS + ((size_t)b * SS + s0) * EE;
#pragma unroll
        for (int it = 0; it < 8; ++it) {
            int g = tid + it * 256;
            int s = (g >> 6) * 2, e4 = (g & 63) * 4;
            float4 v0 = *(const float4*)(eB + (size_t)s * EE + e4);
            float4 v1 = *(const float4*)(eB + (size_t)(s + 1) * EE + e4);
            uint32_t h, l;
            int c = e4 ^ ((s & 7) << 3);
            sp2(v0.x, v0.y, h, l); *(uint32_t*)&eH[s * 256 + c] = h;     *(uint32_t*)&eL[s * 256 + c] = l;
            sp2(v0.z, v0.w, h, l); *(uint32_t*)&eH[s * 256 + c + 2] = h; *(uint32_t*)&eL[s * 256 + c + 2] = l;
            c = e4 ^ (((s + 1) & 7) << 3);
            sp2(v1.x, v1.y, h, l); *(uint32_t*)&eH[(s + 1) * 256 + c] = h;     *(uint32_t*)&eL[(s + 1) * 256 + c] = l;
            sp2(v1.z, v1.w, h, l); *(uint32_t*)&eH[(s + 1) * 256 + c + 2] = h; *(uint32_t*)&eL[(s + 1) * 256 + c + 2] = l;
            float a0[4] = {v0.x, v0.y, v0.z, v0.w};
            float a1[4] = {v1.x, v1.y, v1.z, v1.w};
#pragma unroll
            for (int i2 = 0; i2 < 4; ++i2) {
                int e = e4 + i2;
                sp2(a0[i2], a1[i2], h, l);
                int cc = s ^ ((e & 7) << 3);
                *(uint32_t*)&tH[e * 64 + cc] = h;
                *(uint32_t*)&tL[e * 64 + cc] = l;
            }
        }
        if (tid < 64) sMask[tid] = mask[(size_t)b * SS + s0 + tid];
        __syncthreads();

        // GEMM1: scores[64t][64s], K=256, 3-pass split
        float d1[2][2][4];
#pragma unroll
        for (int mt = 0; mt < 2; ++mt)
#pragma unroll
            for (int nt = 0; nt < 2; ++nt)
#pragma unroll
                for (int q = 0; q < 4; ++q) d1[mt][nt][q] = 0.f;
#pragma unroll 4
        for (int k0 = 0; k0 < 256; k0 += 16) {
            uint32_t aH[2][4], aL2[2][4];
#pragma unroll
            for (int mt = 0; mt < 2; ++mt) {
                int r = wt * 32 + mt * 16 + gid;
                aH[mt][0] = ldA(dH, r, k0 + tig * 2);     aH[mt][1] = ldA(dH, r + 8, k0 + tig * 2);
                aH[mt][2] = ldA(dH, r, k0 + 8 + tig * 2); aH[mt][3] = ldA(dH, r + 8, k0 + 8 + tig * 2);
                aL2[mt][0] = ldA(dL, r, k0 + tig * 2);     aL2[mt][1] = ldA(dL, r + 8, k0 + tig * 2);
                aL2[mt][2] = ldA(dL, r, k0 + 8 + tig * 2); aL2[mt][3] = ldA(dL, r + 8, k0 + 8 + tig * 2);
            }
#pragma unroll
            for (int nt = 0; nt < 2; ++nt) {
                int n = ws * 16 + nt * 8 + gid;
                uint32_t bH[2] = { ldA(eH, n, k0 + tig * 2), ldA(eH, n, k0 + 8 + tig * 2) };
                uint32_t bL[2] = { ldA(eL, n, k0 + tig * 2), ldA(eL, n, k0 + 8 + tig * 2) };
#pragma unroll
                for (int mt = 0; mt < 2; ++mt) {
                    mmab(d1[mt][nt], aH[mt], bH);
                    mmab(d1[mt][nt], aL2[mt], bH);
                    mmab(d1[mt][nt], aH[mt], bL);
                }
            }
        }
        // masked score write
#pragma unroll
        for (int mt = 0; mt < 2; ++mt) {
            int r = wt * 32 + mt * 16 + gid;
#pragma unroll
            for (int nt = 0; nt < 2; ++nt) {
                int n = ws * 16 + nt * 8 + tig * 2;
                bool v0 = sMask[n] != 0, v1 = sMask[n + 1] != 0;
                sP[r * 66 + n]       = v0 ? d1[mt][nt][0] : -INFINITY;
                sP[r * 66 + n + 1]   = v1 ? d1[mt][nt][1] : -INFINITY;
                sP[(r + 8) * 66 + n]     = v0 ? d1[mt][nt][2] : -INFINITY;
                sP[(r + 8) * 66 + n + 1] = v1 ? d1[mt][nt][3] : -INFINITY;
            }
        }
        __syncthreads();

        // online softmax (4 lanes per row, 16 cols each)
        {
            int r = tid >> 2, q = tid & 3;
            float* row = sP + r * 66 + q * 16;
            float v[16];
            float mloc = -INFINITY;
#pragma unroll
            for (int j = 0; j < 16; ++j) { v[j] = row[j]; mloc = fmaxf(mloc, v[j]); }
            mloc = fmaxf(mloc, __shfl_xor_sync(0xffffffffu, mloc, 1));
            mloc = fmaxf(mloc, __shfl_xor_sync(0xffffffffu, mloc, 2));
            float mold = sM[r];
            float mnew = fmaxf(mold, mloc);
            float scale = 1.f, sum = 0.f;
            if (mnew == -INFINITY) {
#pragma unroll
                for (int j = 0; j < 16; ++j) v[j] = 0.f;
            } else {
                scale = __expf(mold - mnew);
#pragma unroll
                for (int j = 0; j < 16; ++j) { v[j] = __expf(v[j] - mnew); sum += v[j]; }
            }
            sum += __shfl_xor_sync(0xffffffffu, sum, 1);
            sum += __shfl_xor_sync(0xffffffffu, sum, 2);
#pragma unroll
            for (int j = 0; j < 16; ++j) row[j] = v[j];
            if (q == 0) { sM[r] = mnew; sLs[r] = sLs[r] * scale + sum; sSc[r] = scale; }
        }
        __syncthreads();

        // P -> bf16 hi/lo + rescale acc
        {
            int r = tid >> 2, q = tid & 3;
#pragma unroll
            for (int j = 0; j < 8; ++j) {
                int c = q * 16 + j * 2;
                float2 p2 = *(float2*)&sP[r * 66 + c];
                uint32_t h, l; sp2(p2.x, p2.y, h, l);
                int cc = c ^ ((r & 7) << 3);
                *(uint32_t*)&pH[r * 64 + cc] = h;
                *(uint32_t*)&pL[r * 64 + cc] = l;
            }
        }
#pragma unroll
        for (int mt = 0; mt < 2; ++mt) {
            int r = wt * 32 + mt * 16 + gid;
            float c0 = sSc[r], c1 = sSc[r + 8];
#pragma unroll
            for (int nt = 0; nt < 8; ++nt) {
                acc[mt][nt][0] *= c0; acc[mt][nt][1] *= c0;
                acc[mt][nt][2] *= c1; acc[mt][nt][3] *= c1;
            }
        }
        __syncthreads();

        // GEMM2: acc += P @ enc, K=64, 3-pass split
#pragma unroll
        for (int k0 = 0; k0 < 64; k0 += 16) {
            uint32_t aH[2][4], aL2[2][4];
#pragma unroll
            for (int mt = 0; mt < 2; ++mt) {
                int r = wt * 32 + mt * 16 + gid;
                aH[mt][0] = ldT(pH, r, k0 + tig * 2);     aH[mt][1] = ldT(pH, r + 8, k0 + tig * 2);
                aH[mt][2] = ldT(pH, r, k0 + 8 + tig * 2); aH[mt][3] = ldT(pH, r + 8, k0 + 8 + tig * 2);
                aL2[mt][0] = ldT(pL, r, k0 + tig * 2);     aL2[mt][1] = ldT(pL, r + 8, k0 + tig * 2);
                aL2[mt][2] = ldT(pL, r, k0 + 8 + tig * 2); aL2[mt][3] = ldT(pL, r + 8, k0 + 8 + tig * 2);
            }
#pragma unroll
            for (int nt = 0; nt < 8; ++nt) {
                int e = ws * 64 + nt * 8 + gid;
                uint32_t bH[2] = { ldT(tH, e, k0 + tig * 2), ldT(tH, e, k0 + 8 + tig * 2) };
                uint32_t bL[2] = { ldT(tL, e, k0 + tig * 2), ldT(tL, e, k0 + 8 + tig * 2) };
#pragma unroll
                for (int mt = 0; mt < 2; ++mt) {
                    mmab(acc[mt][nt], aH[mt], bH);
                    mmab(acc[mt][nt], aL2[mt], bH);
                    mmab(acc[mt][nt], aH[mt], bL);
                }
            }
        }
    }

    // normalize + write context
    float* cB = g_context + ((size_t)b * TT + t0) * EE;
#pragma unroll
    for (int mt = 0; mt < 2; ++mt) {
        int r = wt * 32 + mt * 16 + gid;
        float i0 = 1.f / sLs[r], i1 = 1.f / sLs[r + 8];
#pragma unroll
        for (int nt = 0; nt < 8; ++nt) {
            int e = ws * 64 + nt * 8 + tig * 2;
            *(float2*)(cB + (size_t)r * EE + e) = make_float2(acc[mt][nt][0] * i0, acc[mt][nt][1] * i0);
            *(float2*)(cB + (size_t)(r + 8) * EE + e) = make_float2(acc[mt][nt][2] * i1, acc[mt][nt][3] * i1);
        }
    }
}

// ---------------------------------------------------------------------------
// Kernel 3: out = tanh([context, dec] @ W_fin)
// ---------------------------------------------------------------------------
__global__ __launch_bounds__(256) void k_final(const float* __restrict__ dec,
                                               const float* __restrict__ Wfin,
                                               float* __restrict__ out)
{
    __shared__ float Ast[32][68];
    __shared__ float Bs[32][68];
    const int tid = threadIdx.x;
    const int tx = tid & 15, ty = tid >> 4;
    const int m0 = blockIdx.y * 64, n0 = blockIdx.x * 64;

    u64 acc[2][4];
#pragma unroll
    for (int p = 0; p < 2; ++p)
#pragma unroll
        for (int j = 0; j < 4; ++j) acc[p][j] = 0ull;

    for (int kt = 0; kt < 16; ++kt) {
        int k0 = kt * 32;
        const float* src = (k0 < 256) ? g_context : dec;
        int koff = (k0 < 256) ? k0 : (k0 - 256);
#pragma unroll
        for (int it = 0; it < 2; ++it) {
            int f = tid + it * 256;
            int m = f >> 3, k4 = (f & 7) * 4;
            float4 v = *(const float4*)(src + (size_t)(m0 + m) * 256 + koff + k4);
            Ast[k4 + 0][m] = v.x; Ast[k4 + 1][m] = v.y;
            Ast[k4 + 2][m] = v.z; Ast[k4 + 3][m] = v.w;
        }
#pragma unroll
        for (int it = 0; it < 2; ++it) {
            int f = tid + it * 256;
            int k = f >> 4, n4 = (f & 15) * 4;
            *(float4*)&Bs[k][n4] = *(const float4*)(Wfin + (size_t)(k0 + k) * DD + n0 + n4);
        }
        __syncthreads();
#pragma unroll
        for (int k = 0; k < 32; ++k) {
            ulonglong2 a2 = *(const ulonglong2*)&Ast[k][ty * 4];
            float4 b = *(const float4*)&Bs[k][tx * 4];
            u64 b0 = dup2(b.x), b1 = dup2(b.y), b2 = dup2(b.z), b3 = dup2(b.w);
            fma2(acc[0][0], a2.x, b0); fma2(acc[1][0], a2.y, b0);
            fma2(acc[0][1], a2.x, b1); fma2(acc[1][1], a2.y, b1);
            fma2(acc[0][2], a2.x, b2); fma2(acc[1][2], a2.y, b2);
            fma2(acc[0][3], a2.x, b3); fma2(acc[1][3], a2.y, b3);
        }
        __syncthreads();
    }
    float2 u[2][4];
#pragma unroll
    for (int p = 0; p < 2; ++p)
#pragma unroll
        for (int j = 0; j < 4; ++j) u[p][j] = unpk(acc[p][j]);
    float* o = out + (size_t)(m0 + ty * 4) * DD + n0 + tx * 4;
    *(float4*)(o + 0 * DD) = make_float4(tanhf(u[0][0].x), tanhf(u[0][1].x), tanhf(u[0][2].x), tanhf(u[0][3].x));
    *(float4*)(o + 1 * DD) = make_float4(tanhf(u[0][0].y), tanhf(u[0][1].y), tanhf(u[0][2].y), tanhf(u[0][3].y));
    *(float4*)(o + 2 * DD) = make_float4(tanhf(u[1][0].x), tanhf(u[1][1].x), tanhf(u[1][2].x), tanhf(u[1][3].x));
    *(float4*)(o + 3 * DD) = make_float4(tanhf(u[1][0].y), tanhf(u[1][1].y), tanhf(u[1][2].y), tanhf(u[1][3].y));
}

// ---------------------------------------------------------------------------
extern "C" void kernel_launch(void* const* d_in, const int* in_sizes, int n_in,
                              void* d_out, int out_size)
{
    const float* enc  = (const float*)d_in[0];
    const float* dec  = (const float*)d_in[1];
    const int*   mask = (const int*)d_in[2];
    const float* Wenc = (const float*)d_in[3];
    const float* Wfin = (const float*)d_in[4];
    float* out = (float*)d_out;

    cudaFuncSetAttribute(k_attn, cudaFuncAttributeMaxDynamicSharedMemorySize, SMEM_ATTN_BYTES);

    k_dec_proj<<<dim3(EE / 64, (BB * TT) / 64), 256>>>(dec, Wenc);
    k_attn<<<dim3(TT / 64, BB), 256, SMEM_ATTN_BYTES>>>(enc, mask);
    k_final<<<dim3(DD / 64, (BB * TT) / 64), 256>>>(dec, Wfin, out);
}

// round 12
// speedup vs baseline: 2.6994x; 1.1374x over previous
#include <cuda_runtime.h>
#include <cuda_bf16.h>
#include <math.h>
#include <stdint.h>

#define BB 16
#define SS 2048
#define TT 1024
#define EE 256
#define DD 256

typedef unsigned long long u64;

// bf16 hi/lo operand images, all rows stored with XOR swizzle c ^ ((r&7)<<3)
__device__ __align__(16) uint16_t g_dpH[(size_t)BB * TT * EE];   // decP  [tile][64][256]
__device__ __align__(16) uint16_t g_dpL[(size_t)BB * TT * EE];
__device__ __align__(16) uint16_t g_encH[(size_t)BB * SS * EE];  // enc   [b][s][256]
__device__ __align__(16) uint16_t g_encL[(size_t)BB * SS * EE];
__device__ __align__(16) uint16_t g_etH[(size_t)BB * SS * EE];   // encT  [b][chunk][256e][64s]
__device__ __align__(16) uint16_t g_etL[(size_t)BB * SS * EE];
__device__ __align__(16) uint16_t g_cxH[(size_t)BB * TT * EE];   // ctx   [tile][64][256]
__device__ __align__(16) uint16_t g_cxL[(size_t)BB * TT * EE];
__device__ __align__(16) uint16_t g_dcH[(size_t)BB * TT * DD];   // dec   [tile][64][256]
__device__ __align__(16) uint16_t g_dcL[(size_t)BB * TT * DD];
__device__ __align__(16) uint16_t g_wfH[(size_t)256 * 512];      // WfinT [n(256)][k(512)]
__device__ __align__(16) uint16_t g_wfL[(size_t)256 * 512];

// ---- helpers --------------------------------------------------------------
__device__ __forceinline__ u64 dup2(float x) {
    u64 r; asm("mov.b64 %0, {%1, %1};" : "=l"(r) : "f"(x)); return r;
}
__device__ __forceinline__ void fma2(u64& d, u64 a, u64 b) {
    asm("fma.rn.f32x2 %0, %1, %2, %0;" : "+l"(d) : "l"(a), "l"(b));
}
__device__ __forceinline__ float2 unpk(u64 v) {
    float a, b; asm("mov.b64 {%0, %1}, %2;" : "=f"(a), "=f"(b) : "l"(v));
    return make_float2(a, b);
}
__device__ __forceinline__ void sp2(float a, float b, uint32_t& h, uint32_t& l) {
    __nv_bfloat162 hb = __floats2bfloat162_rn(a, b);
    float2 hf = __bfloat1622float2(hb);
    __nv_bfloat162 lb = __floats2bfloat162_rn(a - hf.x, b - hf.y);
    h = *(uint32_t*)&hb; l = *(uint32_t*)&lb;
}
__device__ __forceinline__ void mmab(float* d, const uint32_t* a, const uint32_t* b) {
    asm volatile("mma.sync.aligned.m16n8k16.row.col.f32.bf16.bf16.f32 "
        "{%0,%1,%2,%3}, {%4,%5,%6,%7}, {%8,%9}, {%0,%1,%2,%3};"
        : "+f"(d[0]), "+f"(d[1]), "+f"(d[2]), "+f"(d[3])
        : "r"(a[0]), "r"(a[1]), "r"(a[2]), "r"(a[3]), "r"(b[0]), "r"(b[1]));
}
__device__ __forceinline__ uint32_t ldA(const uint16_t* p, int r, int c) {   // 256-wide row
    return *(const uint32_t*)&p[r * 256 + (c ^ ((r & 7) << 3))];
}
__device__ __forceinline__ uint32_t ldT(const uint16_t* p, int r, int c) {   // 64-wide row
    return *(const uint32_t*)&p[r * 64 + (c ^ ((r & 7) << 3))];
}

// ---------------------------------------------------------------------------
// k_dec_proj: decP = dec @ W_enc^T (scalar f32x2), epilogue -> bf16 images
// ---------------------------------------------------------------------------
__global__ __launch_bounds__(256) void k_dec_proj(const float* __restrict__ dec,
                                                  const float* __restrict__ W)
{
    __shared__ float Ast[32][68];
    __shared__ float Bs[32][68];
    const int tid = threadIdx.x;
    const int tx = tid & 15, ty = tid >> 4;
    const int m0 = blockIdx.y * 64, n0 = blockIdx.x * 64;

    u64 acc[2][4];
#pragma unroll
    for (int p = 0; p < 2; ++p)
#pragma unroll
        for (int j = 0; j < 4; ++j) acc[p][j] = 0ull;

    for (int k0 = 0; k0 < DD; k0 += 32) {
#pragma unroll
        for (int it = 0; it < 2; ++it) {
            int f = tid + it * 256;
            int m = f >> 3, k4 = (f & 7) * 4;
            float4 v = *(const float4*)(dec + (size_t)(m0 + m) * DD + k0 + k4);
            Ast[k4 + 0][m] = v.x; Ast[k4 + 1][m] = v.y;
            Ast[k4 + 2][m] = v.z; Ast[k4 + 3][m] = v.w;
        }
#pragma unroll
        for (int it = 0; it < 2; ++it) {
            int f = tid + it * 256;
            int e = f >> 3, k4 = (f & 7) * 4;
            float4 v = *(const float4*)(W + (size_t)(n0 + e) * DD + k0 + k4);
            Bs[k4 + 0][e] = v.x; Bs[k4 + 1][e] = v.y;
            Bs[k4 + 2][e] = v.z; Bs[k4 + 3][e] = v.w;
        }
        __syncthreads();
#pragma unroll
        for (int k = 0; k < 32; ++k) {
            ulonglong2 a2 = *(const ulonglong2*)&Ast[k][ty * 4];
            float4 b = *(const float4*)&Bs[k][tx * 4];
            u64 b0 = dup2(b.x), b1 = dup2(b.y), b2 = dup2(b.z), b3 = dup2(b.w);
            fma2(acc[0][0], a2.x, b0); fma2(acc[1][0], a2.y, b0);
            fma2(acc[0][1], a2.x, b1); fma2(acc[1][1], a2.y, b1);
            fma2(acc[0][2], a2.x, b2); fma2(acc[1][2], a2.y, b2);
            fma2(acc[0][3], a2.x, b3); fma2(acc[1][3], a2.y, b3);
        }
        __syncthreads();
    }
    float2 u[2][4];
#pragma unroll
    for (int p = 0; p < 2; ++p)
#pragma unroll
        for (int j = 0; j < 4; ++j) u[p][j] = unpk(acc[p][j]);
    uint16_t* oH = g_dpH + (size_t)blockIdx.y * 16384;
    uint16_t* oL = g_dpL + (size_t)blockIdx.y * 16384;
#pragma unroll
    for (int i = 0; i < 4; ++i) {
        float v0 = (i & 1) ? u[i >> 1][0].y : u[i >> 1][0].x;
        float v1 = (i & 1) ? u[i >> 1][1].y : u[i >> 1][1].x;
        float v2 = (i & 1) ? u[i >> 1][2].y : u[i >> 1][2].x;
        float v3 = (i & 1) ? u[i >> 1][3].y : u[i >> 1][3].x;
        int r = ty * 4 + i;
        int c = (n0 + tx * 4) ^ ((r & 7) << 3);
        uint32_t h, l;
        sp2(v0, v1, h, l); *(uint32_t*)&oH[r * 256 + c] = h;     *(uint32_t*)&oL[r * 256 + c] = l;
        sp2(v2, v3, h, l); *(uint32_t*)&oH[r * 256 + c + 2] = h; *(uint32_t*)&oL[r * 256 + c + 2] = l;
    }
}

// ---------------------------------------------------------------------------
// k_prep: enc -> K-major + transposed bf16 images.  grid (32 chunks, 16 b)
// ---------------------------------------------------------------------------
__global__ __launch_bounds__(256) void k_prep(const float* __restrict__ enc)
{
    __shared__ float sE[64 * 256];
    const int tid = threadIdx.x;
    const int b = blockIdx.y, ch = blockIdx.x, s0 = ch * 64;
    const float* src = enc + ((size_t)b * SS + s0) * EE;
    uint16_t* eH = g_encH + ((size_t)b * SS + s0) * EE;
    uint16_t* eL = g_encL + ((size_t)b * SS + s0) * EE;
#pragma unroll
    for (int it = 0; it < 16; ++it) {
        int f = tid + it * 256;
        int s = f >> 6, e4 = (f & 63) * 4;
        float4 v = *(const float4*)(src + (size_t)s * EE + e4);
        *(float4*)&sE[s * 256 + e4] = v;
        int c = e4 ^ ((s & 7) << 3);
        uint32_t h, l;
        sp2(v.x, v.y, h, l); *(uint32_t*)&eH[s * 256 + c] = h;     *(uint32_t*)&eL[s * 256 + c] = l;
        sp2(v.z, v.w, h, l); *(uint32_t*)&eH[s * 256 + c + 2] = h; *(uint32_t*)&eL[s * 256 + c + 2] = l;
    }
    __syncthreads();
    uint16_t* tH = g_etH + (size_t)(b * 32 + ch) * 16384;
    uint16_t* tL = g_etL + (size_t)(b * 32 + ch) * 16384;
#pragma unroll
    for (int it = 0; it < 32; ++it) {
        int s = it * 2, e = tid;
        uint32_t h, l;
        sp2(sE[s * 256 + e], sE[(s + 1) * 256 + e], h, l);
        int cc = s ^ ((e & 7) << 3);
        *(uint32_t*)&tH[e * 64 + cc] = h;
        *(uint32_t*)&tL[e * 64 + cc] = l;
    }
}

// k_prepd: dec -> bf16 images.  grid (16 tt, 16 b)
__global__ __launch_bounds__(256) void k_prepd(const float* __restrict__ dec)
{
    const int tid = threadIdx.x;
    const int tt = blockIdx.x, b = blockIdx.y;
    const int tile = b * 16 + tt;
    const float* src = dec + ((size_t)b * TT + tt * 64) * DD;
    uint16_t* oH = g_dcH + (size_t)tile * 16384;
    uint16_t* oL = g_dcL + (size_t)tile * 16384;
#pragma unroll
    for (int it = 0; it < 16; ++it) {
        int f = tid + it * 256;
        int t = f >> 6, e4 = (f & 63) * 4;
        float4 v = *(const float4*)(src + (size_t)t * DD + e4);
        int c = e4 ^ ((t & 7) << 3);
        uint32_t h, l;
        sp2(v.x, v.y, h, l); *(uint32_t*)&oH[t * 256 + c] = h;     *(uint32_t*)&oL[t * 256 + c] = l;
        sp2(v.z, v.w, h, l); *(uint32_t*)&oH[t * 256 + c + 2] = h; *(uint32_t*)&oL[t * 256 + c + 2] = l;
    }
}

// k_prepw: Wfin (512,256) -> WfinT images [n][512].  grid (16)
__global__ __launch_bounds__(256) void k_prepw(const float* __restrict__ Wfin)
{
    const int n = threadIdx.x;
#pragma unroll
    for (int i = 0; i < 16; ++i) {
        int k = (blockIdx.x * 16 + i) * 2;
        uint32_t h, l;
        sp2(Wfin[(size_t)k * DD + n], Wfin[(size_t)(k + 1) * DD + n], h, l);
        int c = k ^ ((n & 7) << 3);
        *(uint32_t*)&g_wfH[n * 512 + c] = h;
        *(uint32_t*)&g_wfL[n * 512 + c] = l;
    }
}

// ---------------------------------------------------------------------------
// k_attn: mma.sync bf16 flash attention, all operands from prebuilt images.
// grid (16 ttiles, 16 b), 256 threads (8 warps: 2 t-strips x 4 s/e-strips).
// ---------------------------------------------------------------------------
#define SMEM_ATTN_BYTES 230912

__global__ __launch_bounds__(256, 1) void k_attn(const int* __restrict__ mask)
{
    extern __shared__ unsigned char smraw[];
    uint16_t* eH = (uint16_t*)smraw;          // enc hi  [64 s][256 e]
    uint16_t* eL = eH + 16384;
    uint16_t* tH = eL + 16384;                // encT hi [256 e][64 s]
    uint16_t* tL = tH + 16384;
    uint16_t* dH = tL + 16384;                // decP hi [64 t][256 e]
    uint16_t* dL = dH + 16384;
    float* sP   = (float*)(dL + 16384);       // [64 t][66]
    float* sM   = sP + 64 * 66;
    float* sLs  = sM + 64;
    float* sSc  = sLs + 64;
    int* sMask  = (int*)(sSc + 64);
    uint16_t* pH = (uint16_t*)(sMask + 64);   // P hi [64 t][64 s]
    uint16_t* pL = pH + 4096;

    const int tid = threadIdx.x;
    const int wid = tid >> 5, lane = tid & 31;
    const int gid = lane >> 2, tig = lane & 3;
    const int wt = wid >> 2;
    const int ws = wid & 3;
    const int b = blockIdx.y;
    const int tt = blockIdx.x;
    const int tile = b * 16 + tt;

    // decP images -> smem (pure copy)
    {
        const uint4* sH = (const uint4*)(g_dpH + (size_t)tile * 16384);
        const uint4* sL4 = (const uint4*)(g_dpL + (size_t)tile * 16384);
#pragma unroll
        for (int it = 0; it < 8; ++it) {
            int q = tid + it * 256;
            ((uint4*)dH)[q] = sH[q];
            ((uint4*)dL)[q] = sL4[q];
        }
    }
    if (tid < 64) { sM[tid] = -INFINITY; sLs[tid] = 0.f; }

    float acc[2][8][4];
#pragma unroll
    for (int mt = 0; mt < 2; ++mt)
#pragma unroll
        for (int nt = 0; nt < 8; ++nt)
#pragma unroll
            for (int q = 0; q < 4; ++q) acc[mt][nt][q] = 0.f;

    for (int s0 = 0; s0 < SS; s0 += 64) {
        if (s0 > 0 && mask[(size_t)b * SS + s0] == 0) break;
        __syncthreads();

        // enc chunk images -> smem (pure copies)
        {
            int ch = s0 >> 6;
            const uint4* s1 = (const uint4*)(g_encH + ((size_t)b * SS + s0) * EE);
            const uint4* s2 = (const uint4*)(g_encL + ((size_t)b * SS + s0) * EE);
            const uint4* s3 = (const uint4*)(g_etH + (size_t)(b * 32 + ch) * 16384);
            const uint4* s4 = (const uint4*)(g_etL + (size_t)(b * 32 + ch) * 16384);
#pragma unroll
            for (int it = 0; it < 8; ++it) {
                int q = tid + it * 256;
                ((uint4*)eH)[q] = s1[q];
                ((uint4*)eL)[q] = s2[q];
                ((uint4*)tH)[q] = s3[q];
                ((uint4*)tL)[q] = s4[q];
            }
        }
        if (tid < 64) sMask[tid] = mask[(size_t)b * SS + s0 + tid];
        __syncthreads();

        // GEMM1: scores[64t][64s], K=256, 3-pass split
        float d1[2][2][4];
#pragma unroll
        for (int mt = 0; mt < 2; ++mt)
#pragma unroll
            for (int nt = 0; nt < 2; ++nt)
#pragma unroll
                for (int q = 0; q < 4; ++q) d1[mt][nt][q] = 0.f;
#pragma unroll 4
        for (int k0 = 0; k0 < 256; k0 += 16) {
            uint32_t aH[2][4], aL2[2][4];
#pragma unroll
            for (int mt = 0; mt < 2; ++mt) {
                int r = wt * 32 + mt * 16 + gid;
                aH[mt][0] = ldA(dH, r, k0 + tig * 2);     aH[mt][1] = ldA(dH, r + 8, k0 + tig * 2);
                aH[mt][2] = ldA(dH, r, k0 + 8 + tig * 2); aH[mt][3] = ldA(dH, r + 8, k0 + 8 + tig * 2);
                aL2[mt][0] = ldA(dL, r, k0 + tig * 2);     aL2[mt][1] = ldA(dL, r + 8, k0 + tig * 2);
                aL2[mt][2] = ldA(dL, r, k0 + 8 + tig * 2); aL2[mt][3] = ldA(dL, r + 8, k0 + 8 + tig * 2);
            }
#pragma unroll
            for (int nt = 0; nt < 2; ++nt) {
                int n = ws * 16 + nt * 8 + gid;
                uint32_t bH[2] = { ldA(eH, n, k0 + tig * 2), ldA(eH, n, k0 + 8 + tig * 2) };
                uint32_t bL[2] = { ldA(eL, n, k0 + tig * 2), ldA(eL, n, k0 + 8 + tig * 2) };
#pragma unroll
                for (int mt = 0; mt < 2; ++mt) {
                    mmab(d1[mt][nt], aH[mt], bH);
                    mmab(d1[mt][nt], aL2[mt], bH);
                    mmab(d1[mt][nt], aH[mt], bL);
                }
            }
        }
#pragma unroll
        for (int mt = 0; mt < 2; ++mt) {
            int r = wt * 32 + mt * 16 + gid;
#pragma unroll
            for (int nt = 0; nt < 2; ++nt) {
                int n = ws * 16 + nt * 8 + tig * 2;
                bool v0 = sMask[n] != 0, v1 = sMask[n + 1] != 0;
                sP[r * 66 + n]       = v0 ? d1[mt][nt][0] : -INFINITY;
                sP[r * 66 + n + 1]   = v1 ? d1[mt][nt][1] : -INFINITY;
                sP[(r + 8) * 66 + n]     = v0 ? d1[mt][nt][2] : -INFINITY;
                sP[(r + 8) * 66 + n + 1] = v1 ? d1[mt][nt][3] : -INFINITY;
            }
        }
        __syncthreads();

        // online softmax
        {
            int r = tid >> 2, q = tid & 3;
            float* row = sP + r * 66 + q * 16;
            float v[16];
            float mloc = -INFINITY;
#pragma unroll
            for (int j = 0; j < 16; ++j) { v[j] = row[j]; mloc = fmaxf(mloc, v[j]); }
            mloc = fmaxf(mloc, __shfl_xor_sync(0xffffffffu, mloc, 1));
            mloc = fmaxf(mloc, __shfl_xor_sync(0xffffffffu, mloc, 2));
            float mold = sM[r];
            float mnew = fmaxf(mold, mloc);
            float scale = 1.f, sum = 0.f;
            if (mnew == -INFINITY) {
#pragma unroll
                for (int j = 0; j < 16; ++j) v[j] = 0.f;
            } else {
                scale = __expf(mold - mnew);
#pragma unroll
                for (int j = 0; j < 16; ++j) { v[j] = __expf(v[j] - mnew); sum += v[j]; }
            }
            sum += __shfl_xor_sync(0xffffffffu, sum, 1);
            sum += __shfl_xor_sync(0xffffffffu, sum, 2);
#pragma unroll
            for (int j = 0; j < 16; ++j) row[j] = v[j];
            if (q == 0) { sM[r] = mnew; sLs[r] = sLs[r] * scale + sum; sSc[r] = scale; }
        }
        __syncthreads();

        // P -> bf16 hi/lo + rescale acc
        {
            int r = tid >> 2, q = tid & 3;
#pragma unroll
            for (int j = 0; j < 8; ++j) {
                int c = q * 16 + j * 2;
                float2 p2 = *(float2*)&sP[r * 66 + c];
                uint32_t h, l; sp2(p2.x, p2.y, h, l);
                int cc = c ^ ((r & 7) << 3);
                *(uint32_t*)&pH[r * 64 + cc] = h;
                *(uint32_t*)&pL[r * 64 + cc] = l;
            }
        }
#pragma unroll
        for (int mt = 0; mt < 2; ++mt) {
            int r = wt * 32 + mt * 16 + gid;
            float c0 = sSc[r], c1 = sSc[r + 8];
#pragma unroll
            for (int nt = 0; nt < 8; ++nt) {
                acc[mt][nt][0] *= c0; acc[mt][nt][1] *= c0;
                acc[mt][nt][2] *= c1; acc[mt][nt][3] *= c1;
            }
        }
        __syncthreads();

        // GEMM2: acc += P @ enc, K=64, 3-pass split
#pragma unroll
        for (int k0 = 0; k0 < 64; k0 += 16) {
            uint32_t aH[2][4], aL2[2][4];
#pragma unroll
            for (int mt = 0; mt < 2; ++mt) {
                int r = wt * 32 + mt * 16 + gid;
                aH[mt][0] = ldT(pH, r, k0 + tig * 2);     aH[mt][1] = ldT(pH, r + 8, k0 + tig * 2);
                aH[mt][2] = ldT(pH, r, k0 + 8 + tig * 2); aH[mt][3] = ldT(pH, r + 8, k0 + 8 + tig * 2);
                aL2[mt][0] = ldT(pL, r, k0 + tig * 2);     aL2[mt][1] = ldT(pL, r + 8, k0 + tig * 2);
                aL2[mt][2] = ldT(pL, r, k0 + 8 + tig * 2); aL2[mt][3] = ldT(pL, r + 8, k0 + 8 + tig * 2);
            }
#pragma unroll
            for (int nt = 0; nt < 8; ++nt) {
                int e = ws * 64 + nt * 8 + gid;
                uint32_t bH[2] = { ldT(tH, e, k0 + tig * 2), ldT(tH, e, k0 + 8 + tig * 2) };
                uint32_t bL[2] = { ldT(tL, e, k0 + tig * 2), ldT(tL, e, k0 + 8 + tig * 2) };
#pragma unroll
                for (int mt = 0; mt < 2; ++mt) {
                    mmab(acc[mt][nt], aH[mt], bH);
                    mmab(acc[mt][nt], aL2[mt], bH);
                    mmab(acc[mt][nt], aH[mt], bL);
                }
            }
        }
    }

    // normalize + write context as bf16 hi/lo images
    uint16_t* cH = g_cxH + (size_t)tile * 16384;
    uint16_t* cL = g_cxL + (size_t)tile * 16384;
#pragma unroll
    for (int mt = 0; mt < 2; ++mt) {
        int r = wt * 32 + mt * 16 + gid;
        float i0 = 1.f / sLs[r], i1 = 1.f / sLs[r + 8];
#pragma unroll
        for (int nt = 0; nt < 8; ++nt) {
            int n = ws * 64 + nt * 8 + tig * 2;
            uint32_t h, l;
            sp2(acc[mt][nt][0] * i0, acc[mt][nt][1] * i0, h, l);
            int c = n ^ ((r & 7) << 3);
            *(uint32_t*)&cH[r * 256 + c] = h; *(uint32_t*)&cL[r * 256 + c] = l;
            sp2(acc[mt][nt][2] * i1, acc[mt][nt][3] * i1, h, l);
            int c2 = n ^ (((r + 8) & 7) << 3);
            *(uint32_t*)&cH[(r + 8) * 256 + c2] = h; *(uint32_t*)&cL[(r + 8) * 256 + c2] = l;
        }
    }
}

// ---------------------------------------------------------------------------
// k_final: out = tanh([ctx, dec] @ Wfin), mma.sync bf16, all-copy loads.
// grid (256 m-tiles), 256 threads.
// ---------------------------------------------------------------------------
#define SMEM_FIN_BYTES 81920

__global__ __launch_bounds__(256, 1) void k_final(float* __restrict__ out)
{
    extern __shared__ unsigned char smraw[];
    uint16_t* aHs = (uint16_t*)smraw;        // [64][64]
    uint16_t* aLs = aHs + 4096;
    uint16_t* bHs = aLs + 4096;              // [256][64]
    uint16_t* bLs = bHs + 16384;

    const int tid = threadIdx.x;
    const int wid = tid >> 5, lane = tid & 31;
    const int gid = lane >> 2, tig = lane & 3;
    const int wt = wid >> 2, ws = wid & 3;
    const int tile = blockIdx.x;
    const int m0 = tile * 64;

    float acc[2][8][4];
#pragma unroll
    for (int mt = 0; mt < 2; ++mt)
#pragma unroll
        for (int nt = 0; nt < 8; ++nt)
#pragma unroll
            for (int q = 0; q < 4; ++q) acc[mt][nt][q] = 0.f;

    for (int kt = 0; kt < 8; ++kt) {
        int k0 = kt * 64;
        int koff = (kt < 4) ? k0 : (k0 - 256);
        const uint16_t* srcH = (kt < 4) ? g_cxH : g_dcH;
        const uint16_t* srcL = (kt < 4) ? g_cxL : g_dcL;
        __syncthreads();
        // A copy: 64 rows x 128B, hi+lo = 1024 uint4
#pragma unroll
        for (int it = 0; it < 4; ++it) {
            int q = tid + it * 256;
            int half = q >> 9, r = (q >> 3) & 63, p = q & 7;
            const uint16_t* src = half ? srcL : srcH;
            uint16_t* dst = half ? aLs : aHs;
            ((uint4*)dst)[r * 8 + p] =
                ((const uint4*)(src + ((size_t)tile * 64 + r) * 256 + koff))[p];
        }
        // B copy: 256 rows x 128B, hi+lo = 4096 uint4
#pragma unroll
        for (int it = 0; it < 16; ++it) {
            int q = tid + it * 256;
            int half = q >> 11, n = (q >> 3) & 255, p = q & 7;
            const uint16_t* src = half ? g_wfL : g_wfH;
            uint16_t* dst = half ? bLs : bHs;
            ((uint4*)dst)[n * 8 + p] = ((const uint4*)(src + (size_t)n * 512 + k0))[p];
        }
        __syncthreads();
#pragma unroll
        for (int ks = 0; ks < 4; ++ks) {
            int kk = ks * 16;
            uint32_t aH[2][4], aL2[2][4];
#pragma unroll
            for (int mt = 0; mt < 2; ++mt) {
                int r = wt * 32 + mt * 16 + gid;
                aH[mt][0] = ldT(aHs, r, kk + tig * 2);     aH[mt][1] = ldT(aHs, r + 8, kk + tig * 2);
                aH[mt][2] = ldT(aHs, r, kk + 8 + tig * 2); aH[mt][3] = ldT(aHs, r + 8, kk + 8 + tig * 2);
                aL2[mt][0] = ldT(aLs, r, kk + tig * 2);     aL2[mt][1] = ldT(aLs, r + 8, kk + tig * 2);
                aL2[mt][2] = ldT(aLs, r, kk + 8 + tig * 2); aL2[mt][3] = ldT(aLs, r + 8, kk + 8 + tig * 2);
            }
#pragma unroll
            for (int nt = 0; nt < 8; ++nt) {
                int n = ws * 64 + nt * 8 + gid;
                uint32_t bH[2] = { ldT(bHs, n, kk + tig * 2), ldT(bHs, n, kk + 8 + tig * 2) };
                uint32_t bL[2] = { ldT(bLs, n, kk + tig * 2), ldT(bLs, n, kk + 8 + tig * 2) };
#pragma unroll
                for (int mt = 0; mt < 2; ++mt) {
                    mmab(acc[mt][nt], aH[mt], bH);
                    mmab(acc[mt][nt], aL2[mt], bH);
                    mmab(acc[mt][nt], aH[mt], bL);
                }
            }
        }
    }
#pragma unroll
    for (int mt = 0; mt < 2; ++mt) {
        int r = wt * 32 + mt * 16 + gid;
#pragma unroll
        for (int nt = 0; nt < 8; ++nt) {
            int n = ws * 64 + nt * 8 + tig * 2;
            *(float2*)(out + (size_t)(m0 + r) * DD + n) =
                make_float2(tanhf(acc[mt][nt][0]), tanhf(acc[mt][nt][1]));
            *(float2*)(out + (size_t)(m0 + r + 8) * DD + n) =
                make_float2(tanhf(acc[mt][nt][2]), tanhf(acc[mt][nt][3]));
        }
    }
}

// ---------------------------------------------------------------------------
extern "C" void kernel_launch(void* const* d_in, const int* in_sizes, int n_in,
                              void* d_out, int out_size)
{
    const float* enc  = (const float*)d_in[0];
    const float* dec  = (const float*)d_in[1];
    const int*   mask = (const int*)d_in[2];
    const float* Wenc = (const float*)d_in[3];
    const float* Wfin = (const float*)d_in[4];
    float* out = (float*)d_out;

    cudaFuncSetAttribute(k_attn, cudaFuncAttributeMaxDynamicSharedMemorySize, SMEM_ATTN_BYTES);
    cudaFuncSetAttribute(k_final, cudaFuncAttributeMaxDynamicSharedMemorySize, SMEM_FIN_BYTES);

    k_dec_proj<<<dim3(EE / 64, (BB * TT) / 64), 256>>>(dec, Wenc);
    k_prep<<<dim3(SS / 64, BB), 256>>>(enc);
    k_prepd<<<dim3(TT / 64, BB), 256>>>(dec);
    k_prepw<<<16, 256>>>(Wfin);
    k_attn<<<dim3(TT / 64, BB), 256, SMEM_ATTN_BYTES>>>(mask);
    k_final<<<(BB * TT) / 64, 256, SMEM_FIN_BYTES>>>(out);
}

// round 15
// speedup vs baseline: 3.1259x; 1.1580x over previous
#include <cuda_runtime.h>
#include <cuda_bf16.h>
#include <math.h>
#include <stdint.h>

#define BB 16
#define SS 2048
#define TT 1024
#define EE 256
#define DD 256

// bf16 hi/lo operand images, rows stored with XOR swizzle c ^ ((r&7)<<3)
__device__ __align__(16) uint16_t g_dpH[(size_t)BB * TT * EE];   // decP  [tile][64][256]
__device__ __align__(16) uint16_t g_dpL[(size_t)BB * TT * EE];
__device__ __align__(16) uint16_t g_encH[(size_t)BB * SS * EE];  // enc   [b][s][256]
__device__ __align__(16) uint16_t g_encL[(size_t)BB * SS * EE];
__device__ __align__(16) uint16_t g_etH[(size_t)BB * SS * EE];   // encT  [b][chunk][256e][64s]
__device__ __align__(16) uint16_t g_etL[(size_t)BB * SS * EE];
__device__ __align__(16) uint16_t g_cxH[(size_t)BB * TT * EE];   // ctx   [tile][64][256]
__device__ __align__(16) uint16_t g_cxL[(size_t)BB * TT * EE];
__device__ __align__(16) uint16_t g_dcH[(size_t)BB * TT * DD];   // dec   [tile][64][256]
__device__ __align__(16) uint16_t g_dcL[(size_t)BB * TT * DD];
__device__ __align__(16) uint16_t g_wfH[(size_t)256 * 512];      // WfinT [n(256)][k(512)]
__device__ __align__(16) uint16_t g_wfL[(size_t)256 * 512];
__device__ __align__(16) uint16_t g_weH[(size_t)256 * 256];      // Wenc  [e(256)][d(256)]
__device__ __align__(16) uint16_t g_weL[(size_t)256 * 256];

// ---- helpers --------------------------------------------------------------
__device__ __forceinline__ void sp2(float a, float b, uint32_t& h, uint32_t& l) {
    __nv_bfloat162 hb = __floats2bfloat162_rn(a, b);
    float2 hf = __bfloat1622float2(hb);
    __nv_bfloat162 lb = __floats2bfloat162_rn(a - hf.x, b - hf.y);
    h = *(uint32_t*)&hb; l = *(uint32_t*)&lb;
}
__device__ __forceinline__ void mmab(float* d, const uint32_t* a, const uint32_t* b) {
    asm volatile("mma.sync.aligned.m16n8k16.row.col.f32.bf16.bf16.f32 "
        "{%0,%1,%2,%3}, {%4,%5,%6,%7}, {%8,%9}, {%0,%1,%2,%3};"
        : "+f"(d[0]), "+f"(d[1]), "+f"(d[2]), "+f"(d[3])
        : "r"(a[0]), "r"(a[1]), "r"(a[2]), "r"(a[3]), "r"(b[0]), "r"(b[1]));
}
__device__ __forceinline__ void ldsm4(uint32_t* r, const uint16_t* p) {
    uint32_t a = (uint32_t)__cvta_generic_to_shared(p);
    asm volatile("ldmatrix.sync.aligned.m8n8.x4.shared.b16 {%0,%1,%2,%3}, [%4];"
        : "=r"(r[0]), "=r"(r[1]), "=r"(r[2]), "=r"(r[3]) : "r"(a));
}
// A fragment (a0..a3) for 16x16 block at (rb, k0); w = row width (64/256)
__device__ __forceinline__ void ldA4(uint32_t* r, const uint16_t* b, int rb, int k0, int lane, int w) {
    int sub = lane >> 3;
    int row = rb + (lane & 7) + ((sub & 1) << 3);
    int col = (k0 + ((sub >> 1) << 3)) ^ ((row & 7) << 3);
    ldsm4(r, b + row * w + col);
}
// B fragments for n16 x k16 at (nb, k0): r[0,1]=b0,b1 rows nb..nb+7; r[2,3]=rows nb+8..nb+15
__device__ __forceinline__ void ldB4(uint32_t* r, const uint16_t* b, int nb, int k0, int lane, int w) {
    int sub = lane >> 3;
    int row = nb + (lane & 7) + ((sub >> 1) << 3);
    int col = (k0 + ((sub & 1) << 3)) ^ ((row & 7) << 3);
    ldsm4(r, b + row * w + col);
}

// ---------------------------------------------------------------------------
// prep kernels
// ---------------------------------------------------------------------------
__global__ __launch_bounds__(256) void k_prep(const float* __restrict__ enc)
{
    __shared__ float sE[64 * 256];
    const int tid = threadIdx.x;
    const int b = blockIdx.y, ch = blockIdx.x, s0 = ch * 64;
    const float* src = enc + ((size_t)b * SS + s0) * EE;
    uint16_t* eH = g_encH + ((size_t)b * SS + s0) * EE;
    uint16_t* eL = g_encL + ((size_t)b * SS + s0) * EE;
#pragma unroll
    for (int it = 0; it < 16; ++it) {
        int f = tid + it * 256;
        int s = f >> 6, e4 = (f & 63) * 4;
        float4 v = *(const float4*)(src + (size_t)s * EE + e4);
        *(float4*)&sE[s * 256 + e4] = v;
        int c = e4 ^ ((s & 7) << 3);
        uint32_t h, l;
        sp2(v.x, v.y, h, l); *(uint32_t*)&eH[s * 256 + c] = h;     *(uint32_t*)&eL[s * 256 + c] = l;
        sp2(v.z, v.w, h, l); *(uint32_t*)&eH[s * 256 + c + 2] = h; *(uint32_t*)&eL[s * 256 + c + 2] = l;
    }
    __syncthreads();
    uint16_t* tH = g_etH + (size_t)(b * 32 + ch) * 16384;
    uint16_t* tL = g_etL + (size_t)(b * 32 + ch) * 16384;
#pragma unroll
    for (int it = 0; it < 32; ++it) {
        int s = it * 2, e = tid;
        uint32_t h, l;
        sp2(sE[s * 256 + e], sE[(s + 1) * 256 + e], h, l);
        int cc = s ^ ((e & 7) << 3);
        *(uint32_t*)&tH[e * 64 + cc] = h;
        *(uint32_t*)&tL[e * 64 + cc] = l;
    }
}

__global__ __launch_bounds__(256) void k_prepd(const float* __restrict__ dec)
{
    const int tid = threadIdx.x;
    const int tile = blockIdx.y * 16 + blockIdx.x;
    const float* src = dec + ((size_t)blockIdx.y * TT + blockIdx.x * 64) * DD;
    uint16_t* oH = g_dcH + (size_t)tile * 16384;
    uint16_t* oL = g_dcL + (size_t)tile * 16384;
#pragma unroll
    for (int it = 0; it < 16; ++it) {
        int f = tid + it * 256;
        int t = f >> 6, e4 = (f & 63) * 4;
        float4 v = *(const float4*)(src + (size_t)t * DD + e4);
        int c = e4 ^ ((t & 7) << 3);
        uint32_t h, l;
        sp2(v.x, v.y, h, l); *(uint32_t*)&oH[t * 256 + c] = h;     *(uint32_t*)&oL[t * 256 + c] = l;
        sp2(v.z, v.w, h, l); *(uint32_t*)&oH[t * 256 + c + 2] = h; *(uint32_t*)&oL[t * 256 + c + 2] = l;
    }
}

// Wfin (512,256) -> [n(256)][k(512)] images
__global__ __launch_bounds__(256) void k_prepw(const float* __restrict__ Wfin)
{
    const int n = threadIdx.x;
#pragma unroll
    for (int i = 0; i < 16; ++i) {
        int k = (blockIdx.x * 16 + i) * 2;
        uint32_t h, l;
        sp2(Wfin[(size_t)k * DD + n], Wfin[(size_t)(k + 1) * DD + n], h, l);
        int c = k ^ ((n & 7) << 3);
        *(uint32_t*)&g_wfH[n * 512 + c] = h;
        *(uint32_t*)&g_wfL[n * 512 + c] = l;
    }
}

// Wenc (256,256) natural rows -> [e][d] images
__global__ __launch_bounds__(256) void k_prepwe(const float* __restrict__ Wenc)
{
    const int tid = threadIdx.x;
    const int e = blockIdx.x * 2 + (tid >> 7);
    const int d0 = (tid & 127) * 2;
    uint32_t h, l;
    sp2(Wenc[(size_t)e * DD + d0], Wenc[(size_t)e * DD + d0 + 1], h, l);
    int c = d0 ^ ((e & 7) << 3);
    *(uint32_t*)&g_weH[e * 256 + c] = h;
    *(uint32_t*)&g_weL[e * 256 + c] = l;
}

// ---------------------------------------------------------------------------
// k_dec_proj: decP[t][e] = sum_d dec[t,d] * Wenc[e,d]  (mma.sync bf16 3-pass)
// grid (256 m-tiles), 256 threads. Epilogue -> decP hi/lo images.
// ---------------------------------------------------------------------------
#define SMEM_GEMM_BYTES 81920

__global__ __launch_bounds__(256, 1) void k_dec_proj(void)
{
    extern __shared__ unsigned char smraw[];
    uint16_t* aHs = (uint16_t*)smraw;        // [64][64]
    uint16_t* aLs = aHs + 4096;
    uint16_t* bHs = aLs + 4096;              // [256][64]
    uint16_t* bLs = bHs + 16384;

    const int tid = threadIdx.x;
    const int wid = tid >> 5, lane = tid & 31;
    const int gid = lane >> 2, tig = lane & 3;
    const int wt = wid >> 2, ws = wid & 3;
    const int tile = blockIdx.x;

    float acc[2][8][4];
#pragma unroll
    for (int mt = 0; mt < 2; ++mt)
#pragma unroll
        for (int nt = 0; nt < 8; ++nt)
#pragma unroll
            for (int q = 0; q < 4; ++q) acc[mt][nt][q] = 0.f;

    for (int kt = 0; kt < 4; ++kt) {
        int k0 = kt * 64;
        __syncthreads();
#pragma unroll
        for (int it = 0; it < 4; ++it) {
            int q = tid + it * 256;
            int half = q >> 9, r = (q >> 3) & 63, p = q & 7;
            const uint16_t* src = half ? g_dcL : g_dcH;
            uint16_t* dst = half ? aLs : aHs;
            ((uint4*)dst)[r * 8 + p] = ((const uint4*)(src + ((size_t)tile * 64 + r) * 256 + k0))[p];
        }
#pragma unroll
        for (int it = 0; it < 16; ++it) {
            int q = tid + it * 256;
            int half = q >> 11, n = (q >> 3) & 255, p = q & 7;
            const uint16_t* src = half ? g_weL : g_weH;
            uint16_t* dst = half ? bLs : bHs;
            ((uint4*)dst)[n * 8 + p] = ((const uint4*)(src + (size_t)n * 256 + k0))[p];
        }
        __syncthreads();
#pragma unroll
        for (int ks = 0; ks < 4; ++ks) {
            int kk = ks * 16;
            uint32_t aHf[2][4], aLf[2][4], bHf[4][4], bLf[4][4];
#pragma unroll
            for (int mt = 0; mt < 2; ++mt) {
                ldA4(aHf[mt], aHs, wt * 32 + mt * 16, kk, lane, 64);
                ldA4(aLf[mt], aLs, wt * 32 + mt * 16, kk, lane, 64);
            }
#pragma unroll
            for (int g = 0; g < 4; ++g) {
                ldB4(bHf[g], bHs, ws * 64 + g * 16, kk, lane, 64);
                ldB4(bLf[g], bLs, ws * 64 + g * 16, kk, lane, 64);
            }
#pragma unroll
            for (int nt = 0; nt < 8; ++nt) {
                const uint32_t* bh = &bHf[nt >> 1][(nt & 1) * 2];
                const uint32_t* bl = &bLf[nt >> 1][(nt & 1) * 2];
#pragma unroll
                for (int mt = 0; mt < 2; ++mt) {
                    mmab(acc[mt][nt], aHf[mt], bh);
                    mmab(acc[mt][nt], aLf[mt], bh);
                    mmab(acc[mt][nt], aHf[mt], bl);
                }
            }
        }
    }
    uint16_t* oH = g_dpH + (size_t)tile * 16384;
    uint16_t* oL = g_dpL + (size_t)tile * 16384;
#pragma unroll
    for (int mt = 0; mt < 2; ++mt) {
        int r = wt * 32 + mt * 16 + gid;
#pragma unroll
        for (int nt = 0; nt < 8; ++nt) {
            int n = ws * 64 + nt * 8 + tig * 2;
            uint32_t h, l;
            sp2(acc[mt][nt][0], acc[mt][nt][1], h, l);
            int c = n ^ ((r & 7) << 3);
            *(uint32_t*)&oH[r * 256 + c] = h; *(uint32_t*)&oL[r * 256 + c] = l;
            sp2(acc[mt][nt][2], acc[mt][nt][3], h, l);
            int c2 = n ^ (((r + 8) & 7) << 3);
            *(uint32_t*)&oH[(r + 8) * 256 + c2] = h; *(uint32_t*)&oL[(r + 8) * 256 + c2] = l;
        }
    }
}

// ---------------------------------------------------------------------------
// k_attn: mma.sync bf16 flash attention with ldmatrix fragment loads.
// ---------------------------------------------------------------------------
#define SMEM_ATTN_BYTES 230912

__global__ __launch_bounds__(256, 1) void k_attn(const int* __restrict__ mask)
{
    extern __shared__ unsigned char smraw[];
    uint16_t* eH = (uint16_t*)smraw;          // enc hi  [64 s][256 e]
    uint16_t* eL = eH + 16384;
    uint16_t* tH = eL + 16384;                // encT hi [256 e][64 s]
    uint16_t* tL = tH + 16384;
    uint16_t* dH = tL + 16384;                // decP hi [64 t][256 e]
    uint16_t* dL = dH + 16384;
    float* sP   = (float*)(dL + 16384);       // [64 t][66]
    float* sM   = sP + 64 * 66;
    float* sLs  = sM + 64;
    float* sSc  = sLs + 64;
    int* sMask  = (int*)(sSc + 64);
    uint16_t* pH = (uint16_t*)(sMask + 64);   // P hi [64 t][64 s]
    uint16_t* pL = pH + 4096;

    const int tid = threadIdx.x;
    const int wid = tid >> 5, lane = tid & 31;
    const int gid = lane >> 2, tig = lane & 3;
    const int wt = wid >> 2, ws = wid & 3;
    const int b = blockIdx.y, tt = blockIdx.x;
    const int tile = b * 16 + tt;

    {
        const uint4* sH = (const uint4*)(g_dpH + (size_t)tile * 16384);
        const uint4* sL4 = (const uint4*)(g_dpL + (size_t)tile * 16384);
#pragma unroll
        for (int it = 0; it < 8; ++it) {
            int q = tid + it * 256;
            ((uint4*)dH)[q] = sH[q];
            ((uint4*)dL)[q] = sL4[q];
        }
    }
    if (tid < 64) { sM[tid] = -INFINITY; sLs[tid] = 0.f; }

    float acc[2][8][4];
#pragma unroll
    for (int mt = 0; mt < 2; ++mt)
#pragma unroll
        for (int nt = 0; nt < 8; ++nt)
#pragma unroll
            for (int q = 0; q < 4; ++q) acc[mt][nt][q] = 0.f;

    for (int s0 = 0; s0 < SS; s0 += 64) {
        if (s0 > 0 && mask[(size_t)b * SS + s0] == 0) break;
        __syncthreads();
        {
            int ch = s0 >> 6;
            const uint4* s1 = (const uint4*)(g_encH + ((size_t)b * SS + s0) * EE);
            const uint4* s2 = (const uint4*)(g_encL + ((size_t)b * SS + s0) * EE);
            const uint4* s3 = (const uint4*)(g_etH + (size_t)(b * 32 + ch) * 16384);
            const uint4* s4 = (const uint4*)(g_etL + (size_t)(b * 32 + ch) * 16384);
#pragma unroll
            for (int it = 0; it < 8; ++it) {
                int q = tid + it * 256;
                ((uint4*)eH)[q] = s1[q];
                ((uint4*)eL)[q] = s2[q];
                ((uint4*)tH)[q] = s3[q];
                ((uint4*)tL)[q] = s4[q];
            }
        }
        if (tid < 64) sMask[tid] = mask[(size_t)b * SS + s0 + tid];
        __syncthreads();

        // GEMM1: scores[64t][64s], K=256, 3-pass, ldmatrix loads
        float d1[2][2][4];
#pragma unroll
        for (int mt = 0; mt < 2; ++mt)
#pragma unroll
            for (int nt = 0; nt < 2; ++nt)
#pragma unroll
                for (int q = 0; q < 4; ++q) d1[mt][nt][q] = 0.f;
#pragma unroll 4
        for (int k0 = 0; k0 < 256; k0 += 16) {
            uint32_t aHf[2][4], aLf[2][4], bHf[4], bLf[4];
#pragma unroll
            for (int mt = 0; mt < 2; ++mt) {
                ldA4(aHf[mt], dH, wt * 32 + mt * 16, k0, lane, 256);
                ldA4(aLf[mt], dL, wt * 32 + mt * 16, k0, lane, 256);
            }
            ldB4(bHf, eH, ws * 16, k0, lane, 256);
            ldB4(bLf, eL, ws * 16, k0, lane, 256);
#pragma unroll
            for (int nt = 0; nt < 2; ++nt) {
                const uint32_t* bh = &bHf[nt * 2];
                const uint32_t* bl = &bLf[nt * 2];
#pragma unroll
                for (int mt = 0; mt < 2; ++mt) {
                    mmab(d1[mt][nt], aHf[mt], bh);
                    mmab(d1[mt][nt], aLf[mt], bh);
                    mmab(d1[mt][nt], aHf[mt], bl);
                }
            }
        }
#pragma unroll
        for (int mt = 0; mt < 2; ++mt) {
            int r = wt * 32 + mt * 16 + gid;
#pragma unroll
            for (int nt = 0; nt < 2; ++nt) {
                int n = ws * 16 + nt * 8 + tig * 2;
                bool v0 = sMask[n] != 0, v1 = sMask[n + 1] != 0;
                sP[r * 66 + n]       = v0 ? d1[mt][nt][0] : -INFINITY;
                sP[r * 66 + n + 1]   = v1 ? d1[mt][nt][1] : -INFINITY;
                sP[(r + 8) * 66 + n]     = v0 ? d1[mt][nt][2] : -INFINITY;
                sP[(r + 8) * 66 + n + 1] = v1 ? d1[mt][nt][3] : -INFINITY;
            }
        }
        __syncthreads();

        // online softmax
        {
            int r = tid >> 2, q = tid & 3;
            float* row = sP + r * 66 + q * 16;
            float v[16];
            float mloc = -INFINITY;
#pragma unroll
            for (int j = 0; j < 16; ++j) { v[j] = row[j]; mloc = fmaxf(mloc, v[j]); }
            mloc = fmaxf(mloc, __shfl_xor_sync(0xffffffffu, mloc, 1));
            mloc = fmaxf(mloc, __shfl_xor_sync(0xffffffffu, mloc, 2));
            float mold = sM[r];
            float mnew = fmaxf(mold, mloc);
            float scale = 1.f, sum = 0.f;
            if (mnew == -INFINITY) {
#pragma unroll
                for (int j = 0; j < 16; ++j) v[j] = 0.f;
            } else {
                scale = __expf(mold - mnew);
#pragma unroll
                for (int j = 0; j < 16; ++j) { v[j] = __expf(v[j] - mnew); sum += v[j]; }
            }
            sum += __shfl_xor_sync(0xffffffffu, sum, 1);
            sum += __shfl_xor_sync(0xffffffffu, sum, 2);
#pragma unroll
            for (int j = 0; j < 16; ++j) row[j] = v[j];
            if (q == 0) { sM[r] = mnew; sLs[r] = sLs[r] * scale + sum; sSc[r] = scale; }
        }
        __syncthreads();

        // P -> bf16 hi/lo + rescale acc
        {
            int r = tid >> 2, q = tid & 3;
#pragma unroll
            for (int j = 0; j < 8; ++j) {
                int c = q * 16 + j * 2;
                float2 p2 = *(float2*)&sP[r * 66 + c];
                uint32_t h, l; sp2(p2.x, p2.y, h, l);
                int cc = c ^ ((r & 7) << 3);
                *(uint32_t*)&pH[r * 64 + cc] = h;
                *(uint32_t*)&pL[r * 64 + cc] = l;
            }
        }
#pragma unroll
        for (int mt = 0; mt < 2; ++mt) {
            int r = wt * 32 + mt * 16 + gid;
            float c0 = sSc[r], c1 = sSc[r + 8];
#pragma unroll
            for (int nt = 0; nt < 8; ++nt) {
                acc[mt][nt][0] *= c0; acc[mt][nt][1] *= c0;
                acc[mt][nt][2] *= c1; acc[mt][nt][3] *= c1;
            }
        }
        __syncthreads();

        // GEMM2: acc += P @ enc, K=64, 3-pass, ldmatrix loads
#pragma unroll
        for (int k0 = 0; k0 < 64; k0 += 16) {
            uint32_t aHf[2][4], aLf[2][4], bHf[4][4], bLf[4][4];
#pragma unroll
            for (int mt = 0; mt < 2; ++mt) {
                ldA4(aHf[mt], pH, wt * 32 + mt * 16, k0, lane, 64);
                ldA4(aLf[mt], pL, wt * 32 + mt * 16, k0, lane, 64);
            }
#pragma unroll
            for (int g = 0; g < 4; ++g) {
                ldB4(bHf[g], tH, ws * 64 + g * 16, k0, lane, 64);
                ldB4(bLf[g], tL, ws * 64 + g * 16, k0, lane, 64);
            }
#pragma unroll
            for (int nt = 0; nt < 8; ++nt) {
                const uint32_t* bh = &bHf[nt >> 1][(nt & 1) * 2];
                const uint32_t* bl = &bLf[nt >> 1][(nt & 1) * 2];
#pragma unroll
                for (int mt = 0; mt < 2; ++mt) {
                    mmab(acc[mt][nt], aHf[mt], bh);
                    mmab(acc[mt][nt], aLf[mt], bh);
                    mmab(acc[mt][nt], aHf[mt], bl);
                }
            }
        }
    }

    // normalize + write context images
    uint16_t* cH = g_cxH + (size_t)tile * 16384;
    uint16_t* cL = g_cxL + (size_t)tile * 16384;
#pragma unroll
    for (int mt = 0; mt < 2; ++mt) {
        int r = wt * 32 + mt * 16 + gid;
        float i0 = 1.f / sLs[r], i1 = 1.f / sLs[r + 8];
#pragma unroll
        for (int nt = 0; nt < 8; ++nt) {
            int n = ws * 64 + nt * 8 + tig * 2;
            uint32_t h, l;
            sp2(acc[mt][nt][0] * i0, acc[mt][nt][1] * i0, h, l);
            int c = n ^ ((r & 7) << 3);
            *(uint32_t*)&cH[r * 256 + c] = h; *(uint32_t*)&cL[r * 256 + c] = l;
            sp2(acc[mt][nt][2] * i1, acc[mt][nt][3] * i1, h, l);
            int c2 = n ^ (((r + 8) & 7) << 3);
            *(uint32_t*)&cH[(r + 8) * 256 + c2] = h; *(uint32_t*)&cL[(r + 8) * 256 + c2] = l;
        }
    }
}

// ---------------------------------------------------------------------------
// k_final: out = tanh([ctx, dec] @ Wfin), ldmatrix loads.
// ---------------------------------------------------------------------------
__global__ __launch_bounds__(256, 1) void k_final(float* __restrict__ out)
{
    extern __shared__ unsigned char smraw[];
    uint16_t* aHs = (uint16_t*)smraw;        // [64][64]
    uint16_t* aLs = aHs + 4096;
    uint16_t* bHs = aLs + 4096;              // [256][64]
    uint16_t* bLs = bHs + 16384;

    const int tid = threadIdx.x;
    const int wid = tid >> 5, lane = tid & 31;
    const int gid = lane >> 2, tig = lane & 3;
    const int wt = wid >> 2, ws = wid & 3;
    const int tile = blockIdx.x;
    const int m0 = tile * 64;

    float acc[2][8][4];
#pragma unroll
    for (int mt = 0; mt < 2; ++mt)
#pragma unroll
        for (int nt = 0; nt < 8; ++nt)
#pragma unroll
            for (int q = 0; q < 4; ++q) acc[mt][nt][q] = 0.f;

    for (int kt = 0; kt < 8; ++kt) {
        int k0 = kt * 64;
        int koff = (kt < 4) ? k0 : (k0 - 256);
        const uint16_t* srcH = (kt < 4) ? g_cxH : g_dcH;
        const uint16_t* srcL = (kt < 4) ? g_cxL : g_dcL;
        __syncthreads();
#pragma unroll
        for (int it = 0; it < 4; ++it) {
            int q = tid + it * 256;
            int half = q >> 9, r = (q >> 3) & 63, p = q & 7;
            const uint16_t* src = half ? srcL : srcH;
            uint16_t* dst = half ? aLs : aHs;
            ((uint4*)dst)[r * 8 + p] =
                ((const uint4*)(src + ((size_t)tile * 64 + r) * 256 + koff))[p];
        }
#pragma unroll
        for (int it = 0; it < 16; ++it) {
            int q = tid + it * 256;
            int half = q >> 11, n = (q >> 3) & 255, p = q & 7;
            const uint16_t* src = half ? g_wfL : g_wfH;
            uint16_t* dst = half ? bLs : bHs;
            ((uint4*)dst)[n * 8 + p] = ((const uint4*)(src + (size_t)n * 512 + k0))[p];
        }
        __syncthreads();
#pragma unroll
        for (int ks = 0; ks < 4; ++ks) {
            int kk = ks * 16;
            uint32_t aHf[2][4], aLf[2][4], bHf[4][4], bLf[4][4];
#pragma unroll
            for (int mt = 0; mt < 2; ++mt) {
                ldA4(aHf[mt], aHs, wt * 32 + mt * 16, kk, lane, 64);
                ldA4(aLf[mt], aLs, wt * 32 + mt * 16, kk, lane, 64);
            }
#pragma unroll
            for (int g = 0; g < 4; ++g) {
                ldB4(bHf[g], bHs, ws * 64 + g * 16, kk, lane, 64);
                ldB4(bLf[g], bLs, ws * 64 + g * 16, kk, lane, 64);
            }
#pragma unroll
            for (int nt = 0; nt < 8; ++nt) {
                const uint32_t* bh = &bHf[nt >> 1][(nt & 1) * 2];
                const uint32_t* bl = &bLf[nt >> 1][(nt & 1) * 2];
#pragma unroll
                for (int mt = 0; mt < 2; ++mt) {
                    mmab(acc[mt][nt], aHf[mt], bh);
                    mmab(acc[mt][nt], aLf[mt], bh);
                    mmab(acc[mt][nt], aHf[mt], bl);
                }
            }
        }
    }
#pragma unroll
    for (int mt = 0; mt < 2; ++mt) {
        int r = wt * 32 + mt * 16 + gid;
#pragma unroll
        for (int nt = 0; nt < 8; ++nt) {
            int n = ws * 64 + nt * 8 + tig * 2;
            *(float2*)(out + (size_t)(m0 + r) * DD + n) =
                make_float2(tanhf(acc[mt][nt][0]), tanhf(acc[mt][nt][1]));
            *(float2*)(out + (size_t)(m0 + r + 8) * DD + n) =
                make_float2(tanhf(acc[mt][nt][2]), tanhf(acc[mt][nt][3]));
        }
    }
}

// ---------------------------------------------------------------------------
extern "C" void kernel_launch(void* const* d_in, const int* in_sizes, int n_in,
                              void* d_out, int out_size)
{
    const float* enc  = (const float*)d_in[0];
    const float* dec  = (const float*)d_in[1];
    const int*   mask = (const int*)d_in[2];
    const float* Wenc = (const float*)d_in[3];
    const float* Wfin = (const float*)d_in[4];
    float* out = (float*)d_out;

    cudaFuncSetAttribute(k_attn, cudaFuncAttributeMaxDynamicSharedMemorySize, SMEM_ATTN_BYTES);
    cudaFuncSetAttribute(k_final, cudaFuncAttributeMaxDynamicSharedMemorySize, SMEM_GEMM_BYTES);
    cudaFuncSetAttribute(k_dec_proj, cudaFuncAttributeMaxDynamicSharedMemorySize, SMEM_GEMM_BYTES);

    k_prepd<<<dim3(TT / 64, BB), 256>>>(dec);
    k_prepwe<<<128, 256>>>(Wenc);
    k_prep<<<dim3(SS / 64, BB), 256>>>(enc);
    k_prepw<<<16, 256>>>(Wfin);
    k_dec_proj<<<(BB * TT) / 64, 256, SMEM_GEMM_BYTES>>>();
    k_attn<<<dim3(TT / 64, BB), 256, SMEM_ATTN_BYTES>>>(mask);
    k_final<<<(BB * TT) / 64, 256, SMEM_GEMM_BYTES>>>(out);
}